// round 13
// baseline (speedup 1.0000x reference)
#include <cuda_runtime.h>
#include <cuda_fp16.h>
#include <math_constants.h>
#include <cstdint>

// ---------------------------------------------------------------------------
// MultiHeadAttention, GB300 (family PTX -> mma.sync HMMA):
//   Round 13: GEMMs at 3 CTAs/SM (24 warps) via launch_bounds(256,3) +
//   3-stage cp.async ring (2 chunks in flight). Flash/converts = round 12.
// ---------------------------------------------------------------------------

namespace {
constexpr int TOK   = 4096;
constexpr int D     = 1024;
constexpr int HEADS = 16;
constexpr int SEQ   = 2048;
constexpr int NCH   = D / 32;           // 32 K-chunks of 32
constexpr int TILE_B = 128 * 80;        // 128x32 fp16 tile, 80B rows (10240 B)
constexpr float MASK_NEG = -60.0f;      // 2^-60 -> 0 in fp16
}

// ------------------------------ scratch -----------------------------------
__device__ __half g_xc[TOK * D];               // x fp16
__device__ __half g_cc[TOK * D];               // ctx fp16
__device__ __half g_wqt[D * D];                // W^T fp16
__device__ __half g_wkt[D * D];
__device__ __half g_wvt[D * D];
__device__ __half g_wot[D * D];
__device__ __half g_qc[TOK * HEADS * 64];      // per-head, x(0.125*log2e)
__device__ __half g_kc[TOK * HEADS * 64];
__device__ __half g_vc[TOK * HEADS * 64];

// --------------------------- PTX helpers -----------------------------------
__device__ __forceinline__ uint32_t smem_u32(const void* p) {
    uint32_t a;
    asm("{ .reg .u64 t; cvta.to.shared.u64 t, %1; cvt.u32.u64 %0, t; }"
        : "=r"(a) : "l"(p));
    return a;
}
__device__ __forceinline__ void ldsm_x4(uint32_t* r, uint32_t addr) {
    asm volatile("ldmatrix.sync.aligned.m8n8.x4.shared.b16 {%0,%1,%2,%3}, [%4];"
                 : "=r"(r[0]), "=r"(r[1]), "=r"(r[2]), "=r"(r[3]) : "r"(addr));
}
__device__ __forceinline__ void ldsm_x4t(uint32_t* r, uint32_t addr) {
    asm volatile("ldmatrix.sync.aligned.m8n8.x4.trans.shared.b16 {%0,%1,%2,%3}, [%4];"
                 : "=r"(r[0]), "=r"(r[1]), "=r"(r[2]), "=r"(r[3]) : "r"(addr));
}
__device__ __forceinline__ void mma16816(float* d, const uint32_t* a,
                                         uint32_t b0, uint32_t b1) {
    asm volatile(
        "mma.sync.aligned.m16n8k16.row.col.f32.f16.f16.f32 "
        "{%0,%1,%2,%3}, {%4,%5,%6,%7}, {%8,%9}, {%0,%1,%2,%3};"
        : "+f"(d[0]), "+f"(d[1]), "+f"(d[2]), "+f"(d[3])
        : "r"(a[0]), "r"(a[1]), "r"(a[2]), "r"(a[3]), "r"(b0), "r"(b1));
}
__device__ __forceinline__ uint32_t packh(float a, float b) {
    __half2 h = __floats2half2_rn(a, b);
    return *(uint32_t*)&h;
}
__device__ __forceinline__ uint32_t ex2_h2(uint32_t s) {
    uint32_t r;
    asm("ex2.approx.f16x2 %0, %1;" : "=r"(r) : "r"(s));
    return r;
}
__device__ __forceinline__ void cpa16(uint32_t dst, const void* src) {
    asm volatile("cp.async.cg.shared.global [%0], [%1], 16;"
                 :: "r"(dst), "l"(src) : "memory");
}
#define CP_COMMIT() asm volatile("cp.async.commit_group;" ::: "memory")
#define CP_WAIT(N)  asm volatile("cp.async.wait_group %0;" :: "n"(N) : "memory")

// ---------------------------------------------------------------------------
// Merged converts: z=0..3 weight transpose, z=4 x convert.
// ---------------------------------------------------------------------------
__global__ void convert_all(const float* __restrict__ x,
                            const float* __restrict__ W0,
                            const float* __restrict__ W1,
                            const float* __restrict__ W2,
                            const float* __restrict__ W3,
                            __half* __restrict__ xc,
                            __half* __restrict__ T0,
                            __half* __restrict__ T1,
                            __half* __restrict__ T2,
                            __half* __restrict__ T3)
{
    const int z = blockIdx.z;
    if (z == 4) {
        int idx = (blockIdx.y * 32 + blockIdx.x) * 256 + threadIdx.x;
        const int stride = 32 * 32 * 256;
#pragma unroll
        for (int i = 0; i < TOK * D / (32 * 32 * 256); i++) {
            xc[idx] = __float2half_rn(x[idx]);
            idx += stride;
        }
        return;
    }
    __shared__ float tile[32][33];
    const float* W = z == 0 ? W0 : (z == 1 ? W1 : (z == 2 ? W2 : W3));
    __half* Wt = z == 0 ? T0 : (z == 1 ? T1 : (z == 2 ? T2 : T3));

    const int k0 = blockIdx.y * 32;
    const int n0 = blockIdx.x * 32;
    const int tx = threadIdx.x & 31;
    const int ty = threadIdx.x >> 5;
#pragma unroll
    for (int p = 0; p < 4; p++)
        tile[ty + p * 8][tx] = W[(size_t)(k0 + ty + p * 8) * D + n0 + tx];
    __syncthreads();
#pragma unroll
    for (int p = 0; p < 4; p++) {
        int n = n0 + ty + p * 8;
        Wt[(size_t)n * D + k0 + tx] = __float2half_rn(tile[tx][ty + p * 8]);
    }
}

// ---------------------------------------------------------------------------
// Single-term fp16 GEMM: 128x128 tile, BK=32, 8 warps, 3-stage cp.async,
// 3 CTAs/SM (launch_bounds-capped regs).
// MODE 1 (QKV): z picks W / out / scale; per-head fp16 out.
// MODE 0 (out): fp32 out + bias.
// ---------------------------------------------------------------------------
template <int MODE>
__global__ __launch_bounds__(256, 3)
void gemm_1t(const __half* __restrict__ A,
             const __half* __restrict__ B0,
             const __half* __restrict__ B1,
             const __half* __restrict__ B2,
             const float* __restrict__ bias,
             float* __restrict__ C,
             __half* __restrict__ O0,
             __half* __restrict__ O1,
             __half* __restrict__ O2)
{
    extern __shared__ char dsm[];
    const uint32_t sS = smem_u32(dsm);
    constexpr uint32_t STG = 2 * TILE_B;     // A tile + B tile (20480 B)

    const int t = threadIdx.x, lane = t & 31, warp = t >> 5;
    const int wm = (warp & 1) * 64, wn = (warp >> 1) * 32;
    const int m0 = blockIdx.y * 128, n0 = blockIdx.x * 128;

    const __half* Bt;
    __half* Cb = nullptr;
    float scale = 1.f;
    int z = 0;
    if (MODE == 1) {
        z = blockIdx.z;
        Bt = z == 0 ? B0 : (z == 1 ? B1 : B2);
        Cb = z == 0 ? O0 : (z == 1 ? O1 : O2);
        scale = (z == 0) ? 0.125f * 1.44269504f : 1.f;   // fold log2(e) into Q
    } else {
        Bt = B0;
    }

    const int r0 = t >> 2,         c0 = (t & 3) * 8;
    const int r1 = (t + 256) >> 2, c1 = ((t + 256) & 3) * 8;

    const __half* Ag0 = A  + (size_t)(m0 + r0) * D + c0;
    const __half* Ag1 = A  + (size_t)(m0 + r1) * D + c1;
    const __half* Bg0 = Bt + (size_t)(n0 + r0) * D + c0;
    const __half* Bg1 = Bt + (size_t)(n0 + r1) * D + c1;

    const uint32_t d0 = (uint32_t)(r0 * 80 + c0 * 2);
    const uint32_t d1 = (uint32_t)(r1 * 80 + c1 * 2);

    auto issue = [&](int st, int ch) {
        const int off = ch * 32;
        const uint32_t b = sS + st * STG;
        cpa16(b + d0, Ag0 + off);
        cpa16(b + d1, Ag1 + off);
        cpa16(b + TILE_B + d0, Bg0 + off);
        cpa16(b + TILE_B + d1, Bg1 + off);
    };

    issue(0, 0); CP_COMMIT();
    issue(1, 1); CP_COMMIT();

    const uint32_t a_off = (uint32_t)((wm + (lane & 15)) * 80 + (lane >> 4) * 16);
    const uint32_t b_off = (uint32_t)(TILE_B +
                                      (wn + (lane & 15)) * 80 + (lane >> 4) * 16);

    float acc[4][4][4];
#pragma unroll
    for (int i = 0; i < 4; i++)
#pragma unroll
        for (int j = 0; j < 4; j++)
#pragma unroll
            for (int u = 0; u < 4; u++) acc[i][j][u] = 0.f;

    int st = 0;
    for (int c = 0; c < NCH; c++) {
        if (c + 2 < NCH) issue((c + 2) % 3, c + 2);
        CP_COMMIT();
        CP_WAIT(2);
        __syncthreads();

        const uint32_t sbase = sS + (uint32_t)(st * STG);
#pragma unroll
        for (int kk = 0; kk < 2; kk++) {
            uint32_t af[4][4], bf[2][4];
#pragma unroll
            for (int mt = 0; mt < 4; mt++)
                ldsm_x4(af[mt], sbase + a_off + (uint32_t)(mt * 16 * 80 + kk * 32));
#pragma unroll
            for (int nb = 0; nb < 2; nb++)
                ldsm_x4(bf[nb], sbase + b_off + (uint32_t)(nb * 16 * 80 + kk * 32));
#pragma unroll
            for (int mt = 0; mt < 4; mt++)
#pragma unroll
                for (int n8 = 0; n8 < 4; n8++) {
                    const int nb = n8 >> 1, hi = n8 & 1;
                    mma16816(acc[mt][n8], af[mt],
                             bf[nb][hi ? 1 : 0], bf[nb][hi ? 3 : 2]);
                }
        }
        __syncthreads();
        st = (st + 1) % 3;
    }

    const int er = lane >> 2;
    const int ec = (lane & 3) * 2;
#pragma unroll
    for (int mt = 0; mt < 4; mt++) {
#pragma unroll
        for (int n8 = 0; n8 < 4; n8++) {
            const int row = m0 + wm + mt * 16 + er;
            const int col = n0 + wn + n8 * 8 + ec;
            if (MODE == 0) {
                float2 bb = *(const float2*)&bias[col];
                *(float2*)&C[(size_t)row * D + col] =
                    make_float2(acc[mt][n8][0] + bb.x, acc[mt][n8][1] + bb.y);
                *(float2*)&C[(size_t)(row + 8) * D + col] =
                    make_float2(acc[mt][n8][2] + bb.x, acc[mt][n8][3] + bb.y);
            } else {
                const int h = col >> 6, d = col & 63;
                *(uint32_t*)&Cb[((size_t)row * HEADS + h) * 64 + d] =
                    packh(acc[mt][n8][0] * scale, acc[mt][n8][1] * scale);
                *(uint32_t*)&Cb[((size_t)(row + 8) * HEADS + h) * 64 + d] =
                    packh(acc[mt][n8][2] * scale, acc[mt][n8][3] * scale);
            }
        }
    }
}

// ---------------------------------------------------------------------------
// Flash attention, fixed-max softmax via ex2.approx.f16x2, 128-query tile,
// 8 warps, 3-stage 64-key cp.async K/V pipeline (two tiles in flight).
// smem: qs 18432 + ks 3x9216 + vs 3x9216 = 73728 B (2 CTAs/SM).
// ---------------------------------------------------------------------------
__global__ __launch_bounds__(256, 2)
void flash_mma(const __half* __restrict__ qc,
               const __half* __restrict__ kc,
               const __half* __restrict__ vc,
               __half* __restrict__ cc)
{
    extern __shared__ __half fsm[];
    __half* qs = fsm;                              // 128*72
    const uint32_t qs_b = smem_u32(fsm);
    const uint32_t ks_b = qs_b + 18432u;
    const uint32_t vs_b = ks_b + 27648u;           // 3 stages of 9216

    const int t = threadIdx.x, lane = t & 31, w = t >> 5;
    const int qt = (int)gridDim.x - 1 - (int)blockIdx.x;   // heavy blocks first
    const int b  = blockIdx.y >> 4, h = blockIdx.y & 15;
    const int q0 = qt * 128;
    const size_t tokbase = (size_t)b * SEQ;

    auto issueKV = [&](int kt) {
        const int s = kt % 3;
        const __half* kg = kc + ((tokbase + kt * 64) * HEADS + h) * 64;
        const __half* vg = vc + ((tokbase + kt * 64) * HEADS + h) * 64;
#pragma unroll
        for (int p = 0; p < 2; p++) {
            int idx = p * 256 + t;
            int row = idx >> 3, c8 = idx & 7;
            uint32_t doff = (uint32_t)(s * 9216 + row * 144 + c8 * 16);
            size_t soff = (size_t)row * (HEADS * 64) + c8 * 8;
            cpa16(ks_b + doff, kg + soff);
            cpa16(vs_b + doff, vg + soff);
        }
    };

    // load Q tile: 128 rows x 64 halves = 1024 8-half chunks
    const __half* qg = qc + ((tokbase + q0) * HEADS + h) * 64;
#pragma unroll
    for (int it = 0; it < 4; it++) {
        int idx = it * 256 + t;
        int row = idx >> 3, c8 = (idx & 7) * 8;
        *(uint4*)&qs[row * 72 + c8] =
            *(const uint4*)&qg[(size_t)row * (HEADS * 64) + c8];
    }
    const int n_kt = 2 * qt + 2;
    issueKV(0); CP_COMMIT();
    issueKV(1); CP_COMMIT();               // n_kt >= 2 always
    __syncthreads();

    uint32_t qf[4][4];
    const uint32_t qbase = qs_b +
        (uint32_t)((w * 16 + (lane & 15)) * 144 + (lane >> 4) * 16);
#pragma unroll
    for (int c = 0; c < 4; c++) ldsm_x4(qf[c], qbase + c * 32);

    const int er = lane >> 2, ec = (lane & 3) * 2;
    const int wq_min = q0 + w * 16;
    float l0 = 0.f, l1 = 0.f;
    float oa[8][4];
#pragma unroll
    for (int i = 0; i < 8; i++)
#pragma unroll
        for (int j = 0; j < 4; j++) oa[i][j] = 0.f;

    for (int kt = 0; kt < n_kt; kt++) {
        if (kt + 2 < n_kt) { issueKV(kt + 2); CP_COMMIT(); CP_WAIT(2); }
        else if (kt + 1 < n_kt) { CP_WAIT(1); }
        else { CP_WAIT(0); }
        __syncthreads();

        const int k0 = kt * 64;
        const int s = kt % 3;

        if (k0 <= wq_min + 15) {
            // ---- S = Q K^T (log2 domain) ----
            float sa[8][4];
#pragma unroll
            for (int i = 0; i < 8; i++)
#pragma unroll
                for (int j = 0; j < 4; j++) sa[i][j] = 0.f;

            const uint32_t kb = ks_b + (uint32_t)(s * 9216) +
                (uint32_t)((lane & 15) * 144 + (lane >> 4) * 16);
#pragma unroll
            for (int nb = 0; nb < 4; nb++) {
                const uint32_t roff = (uint32_t)(nb * 16 * 144);
#pragma unroll
                for (int c = 0; c < 4; c++) {
                    uint32_t bf_[4];
                    ldsm_x4(bf_, kb + roff + c * 32);
                    mma16816(sa[nb * 2],     qf[c], bf_[0], bf_[2]);
                    mma16816(sa[nb * 2 + 1], qf[c], bf_[1], bf_[3]);
                }
            }

            // ---- causal mask (finite large-negative -> fp16 flush to 0) ----
            if (k0 + 63 > wq_min) {
                const int gq0 = wq_min + er;
#pragma unroll
                for (int n8 = 0; n8 < 8; n8++) {
                    const int gk = k0 + n8 * 8 + ec;
                    if (gk > gq0)         sa[n8][0] = MASK_NEG;
                    if (gk + 1 > gq0)     sa[n8][1] = MASK_NEG;
                    if (gk > gq0 + 8)     sa[n8][2] = MASK_NEG;
                    if (gk + 1 > gq0 + 8) sa[n8][3] = MASK_NEG;
                }
            }

            // ---- p = 2^s in fp16 pairs; packed P = PV A-fragments ----
            uint32_t p01[8], p23[8];
            __half2 lh0 = __floats2half2_rn(0.f, 0.f);
            __half2 lh1 = lh0;
#pragma unroll
            for (int n8 = 0; n8 < 8; n8++) {
                p01[n8] = ex2_h2(packh(sa[n8][0], sa[n8][1]));
                p23[n8] = ex2_h2(packh(sa[n8][2], sa[n8][3]));
                lh0 = __hadd2(lh0, *(__half2*)&p01[n8]);
                lh1 = __hadd2(lh1, *(__half2*)&p23[n8]);
            }
            float2 lf0 = __half22float2(lh0);
            float2 lf1 = __half22float2(lh1);
            l0 += lf0.x + lf0.y;
            l1 += lf1.x + lf1.y;

            // ---- O += P V ----
            const uint32_t vb0 = vs_b + (uint32_t)(s * 9216) +
                (uint32_t)((lane & 15) * 144 + (lane >> 4) * 16);
#pragma unroll
            for (int c = 0; c < 4; c++) {
                uint32_t ah[4];
                ah[0] = p01[2 * c];
                ah[1] = p23[2 * c];
                ah[2] = p01[2 * c + 1];
                ah[3] = p23[2 * c + 1];
                const uint32_t kroff = (uint32_t)(c * 16 * 144);
#pragma unroll
                for (int vb = 0; vb < 4; vb++) {
                    uint32_t bf_[4];
                    ldsm_x4t(bf_, vb0 + kroff + vb * 32);
                    mma16816(oa[vb * 2],     ah, bf_[0], bf_[1]);
                    mma16816(oa[vb * 2 + 1], ah, bf_[2], bf_[3]);
                }
            }
        }
        __syncthreads();
    }

    // ---- final row-sum reduction across the 4-lane quad ----
    l0 += __shfl_xor_sync(0xffffffffu, l0, 1);
    l0 += __shfl_xor_sync(0xffffffffu, l0, 2);
    l1 += __shfl_xor_sync(0xffffffffu, l1, 1);
    l1 += __shfl_xor_sync(0xffffffffu, l1, 2);

    // ---- epilogue: ctx = O / l -> cc [tok][1024] fp16 ----
    const float il0 = 1.f / l0, il1 = 1.f / l1;
    const int gq0 = wq_min + er;
    const size_t rbase0 = (tokbase + gq0) * (size_t)D;
    const size_t rbase1 = (tokbase + gq0 + 8) * (size_t)D;
#pragma unroll
    for (int n8 = 0; n8 < 8; n8++) {
        const int col = h * 64 + n8 * 8 + ec;
        *(uint32_t*)&cc[rbase0 + col] = packh(oa[n8][0] * il0, oa[n8][1] * il0);
        *(uint32_t*)&cc[rbase1 + col] = packh(oa[n8][2] * il1, oa[n8][3] * il1);
    }
}

// ---------------------------------------------------------------------------
extern "C" void kernel_launch(void* const* d_in, const int* in_sizes, int n_in,
                              void* d_out, int out_size)
{
    const float* x  = (const float*)d_in[0];
    const float* Wq = (const float*)d_in[1];
    const float* Wk = (const float*)d_in[2];
    const float* Wv = (const float*)d_in[3];
    const float* Wo = (const float*)d_in[4];
    const float* bo = (const float*)d_in[5];
    float* out = (float*)d_out;

    __half *xc, *cc, *wqt, *wkt, *wvt, *wot, *qc, *kc, *vc;
    cudaGetSymbolAddress((void**)&xc,  g_xc);
    cudaGetSymbolAddress((void**)&cc,  g_cc);
    cudaGetSymbolAddress((void**)&wqt, g_wqt);
    cudaGetSymbolAddress((void**)&wkt, g_wkt);
    cudaGetSymbolAddress((void**)&wvt, g_wvt);
    cudaGetSymbolAddress((void**)&wot, g_wot);
    cudaGetSymbolAddress((void**)&qc,  g_qc);
    cudaGetSymbolAddress((void**)&kc,  g_kc);
    cudaGetSymbolAddress((void**)&vc,  g_vc);

    const int GEMM_SMEM  = 3 * 2 * TILE_B;              // 61440 B (3 stages)
    const int FLASH_SMEM = 18432 + 2 * 27648;           // 73728 B
    cudaFuncSetAttribute(gemm_1t<0>,
        cudaFuncAttributeMaxDynamicSharedMemorySize, GEMM_SMEM);
    cudaFuncSetAttribute(gemm_1t<1>,
        cudaFuncAttributeMaxDynamicSharedMemorySize, GEMM_SMEM);
    cudaFuncSetAttribute(flash_mma,
        cudaFuncAttributeMaxDynamicSharedMemorySize, FLASH_SMEM);

    convert_all<<<dim3(32, 32, 5), 256>>>(x, Wq, Wk, Wv, Wo,
                                          xc, wqt, wkt, wvt, wot);

    gemm_1t<1><<<dim3(D / 128, TOK / 128, 3), 256, GEMM_SMEM>>>(
        xc, wqt, wkt, wvt, nullptr, nullptr, qc, kc, vc);

    flash_mma<<<dim3(SEQ / 128, 2 * HEADS), 256, FLASH_SMEM>>>(qc, kc, vc, cc);

    gemm_1t<0><<<dim3(D / 128, TOK / 128), 256, GEMM_SMEM>>>(
        cc, wot, nullptr, nullptr, bo, out, nullptr, nullptr, nullptr);
}

// round 14
// speedup vs baseline: 1.3597x; 1.3597x over previous
#include <cuda_runtime.h>
#include <cuda_fp16.h>
#include <math_constants.h>
#include <cstdint>

// ---------------------------------------------------------------------------
// MultiHeadAttention, GB300 (family PTX -> mma.sync HMMA):
//   Round 14: round-12 design with deeper pipelines only —
//   GEMM 5-stage (4 chunks in flight), flash 4-stage K/V (3 in flight).
// ---------------------------------------------------------------------------

namespace {
constexpr int TOK   = 4096;
constexpr int D     = 1024;
constexpr int HEADS = 16;
constexpr int SEQ   = 2048;
constexpr int NCH   = D / 32;           // 32 K-chunks of 32
constexpr int TILE_B = 128 * 80;        // 128x32 fp16 tile, 80B rows (10240 B)
constexpr float MASK_NEG = -60.0f;      // 2^-60 -> 0 in fp16
}

// ------------------------------ scratch -----------------------------------
__device__ __half g_xc[TOK * D];               // x fp16
__device__ __half g_cc[TOK * D];               // ctx fp16
__device__ __half g_wqt[D * D];                // W^T fp16
__device__ __half g_wkt[D * D];
__device__ __half g_wvt[D * D];
__device__ __half g_wot[D * D];
__device__ __half g_qc[TOK * HEADS * 64];      // per-head, x(0.125*log2e)
__device__ __half g_kc[TOK * HEADS * 64];
__device__ __half g_vc[TOK * HEADS * 64];

// --------------------------- PTX helpers -----------------------------------
__device__ __forceinline__ uint32_t smem_u32(const void* p) {
    uint32_t a;
    asm("{ .reg .u64 t; cvta.to.shared.u64 t, %1; cvt.u32.u64 %0, t; }"
        : "=r"(a) : "l"(p));
    return a;
}
__device__ __forceinline__ void ldsm_x4(uint32_t* r, uint32_t addr) {
    asm volatile("ldmatrix.sync.aligned.m8n8.x4.shared.b16 {%0,%1,%2,%3}, [%4];"
                 : "=r"(r[0]), "=r"(r[1]), "=r"(r[2]), "=r"(r[3]) : "r"(addr));
}
__device__ __forceinline__ void ldsm_x4t(uint32_t* r, uint32_t addr) {
    asm volatile("ldmatrix.sync.aligned.m8n8.x4.trans.shared.b16 {%0,%1,%2,%3}, [%4];"
                 : "=r"(r[0]), "=r"(r[1]), "=r"(r[2]), "=r"(r[3]) : "r"(addr));
}
__device__ __forceinline__ void mma16816(float* d, const uint32_t* a,
                                         uint32_t b0, uint32_t b1) {
    asm volatile(
        "mma.sync.aligned.m16n8k16.row.col.f32.f16.f16.f32 "
        "{%0,%1,%2,%3}, {%4,%5,%6,%7}, {%8,%9}, {%0,%1,%2,%3};"
        : "+f"(d[0]), "+f"(d[1]), "+f"(d[2]), "+f"(d[3])
        : "r"(a[0]), "r"(a[1]), "r"(a[2]), "r"(a[3]), "r"(b0), "r"(b1));
}
__device__ __forceinline__ uint32_t packh(float a, float b) {
    __half2 h = __floats2half2_rn(a, b);
    return *(uint32_t*)&h;
}
__device__ __forceinline__ uint32_t ex2_h2(uint32_t s) {
    uint32_t r;
    asm("ex2.approx.f16x2 %0, %1;" : "=r"(r) : "r"(s));
    return r;
}
__device__ __forceinline__ void cpa16(uint32_t dst, const void* src) {
    asm volatile("cp.async.cg.shared.global [%0], [%1], 16;"
                 :: "r"(dst), "l"(src) : "memory");
}
#define CP_COMMIT() asm volatile("cp.async.commit_group;" ::: "memory")
#define CP_WAIT(N)  asm volatile("cp.async.wait_group %0;" :: "n"(N) : "memory")

// ---------------------------------------------------------------------------
// Merged converts: z=0..3 weight transpose, z=4 x convert.
// ---------------------------------------------------------------------------
__global__ void convert_all(const float* __restrict__ x,
                            const float* __restrict__ W0,
                            const float* __restrict__ W1,
                            const float* __restrict__ W2,
                            const float* __restrict__ W3,
                            __half* __restrict__ xc,
                            __half* __restrict__ T0,
                            __half* __restrict__ T1,
                            __half* __restrict__ T2,
                            __half* __restrict__ T3)
{
    const int z = blockIdx.z;
    if (z == 4) {
        int idx = (blockIdx.y * 32 + blockIdx.x) * 256 + threadIdx.x;
        const int stride = 32 * 32 * 256;
#pragma unroll
        for (int i = 0; i < TOK * D / (32 * 32 * 256); i++) {
            xc[idx] = __float2half_rn(x[idx]);
            idx += stride;
        }
        return;
    }
    __shared__ float tile[32][33];
    const float* W = z == 0 ? W0 : (z == 1 ? W1 : (z == 2 ? W2 : W3));
    __half* Wt = z == 0 ? T0 : (z == 1 ? T1 : (z == 2 ? T2 : T3));

    const int k0 = blockIdx.y * 32;
    const int n0 = blockIdx.x * 32;
    const int tx = threadIdx.x & 31;
    const int ty = threadIdx.x >> 5;
#pragma unroll
    for (int p = 0; p < 4; p++)
        tile[ty + p * 8][tx] = W[(size_t)(k0 + ty + p * 8) * D + n0 + tx];
    __syncthreads();
#pragma unroll
    for (int p = 0; p < 4; p++) {
        int n = n0 + ty + p * 8;
        Wt[(size_t)n * D + k0 + tx] = __float2half_rn(tile[tx][ty + p * 8]);
    }
}

// ---------------------------------------------------------------------------
// Single-term fp16 GEMM core: 128x128 tile, BK=32, 8 warps, cp.async 5-stage
// (4 chunks in flight).
// MODE 1 (QKV): z picks W / out / scale; per-head fp16 out.
// MODE 0 (out): fp32 out + bias, A = ctx fp16 [tok][1024].
// ---------------------------------------------------------------------------
template <int MODE>
__global__ __launch_bounds__(256)
void gemm_1t(const __half* __restrict__ A,
             const __half* __restrict__ B0,
             const __half* __restrict__ B1,
             const __half* __restrict__ B2,
             const float* __restrict__ bias,
             float* __restrict__ C,
             __half* __restrict__ O0,
             __half* __restrict__ O1,
             __half* __restrict__ O2)
{
    extern __shared__ char dsm[];
    const uint32_t sS = smem_u32(dsm);
    constexpr uint32_t STG = 2 * TILE_B;     // A tile + B tile (20480 B)

    const int t = threadIdx.x, lane = t & 31, warp = t >> 5;
    const int wm = (warp & 1) * 64, wn = (warp >> 1) * 32;
    const int m0 = blockIdx.y * 128, n0 = blockIdx.x * 128;

    const __half* Bt;
    __half* Cb = nullptr;
    float scale = 1.f;
    int z = 0;
    if (MODE == 1) {
        z = blockIdx.z;
        Bt = z == 0 ? B0 : (z == 1 ? B1 : B2);
        Cb = z == 0 ? O0 : (z == 1 ? O1 : O2);
        scale = (z == 0) ? 0.125f * 1.44269504f : 1.f;   // fold log2(e) into Q
    } else {
        Bt = B0;
    }

    const int r0 = t >> 2,         c0 = (t & 3) * 8;
    const int r1 = (t + 256) >> 2, c1 = ((t + 256) & 3) * 8;

    const __half* Ag0 = A  + (size_t)(m0 + r0) * D + c0;
    const __half* Ag1 = A  + (size_t)(m0 + r1) * D + c1;
    const __half* Bg0 = Bt + (size_t)(n0 + r0) * D + c0;
    const __half* Bg1 = Bt + (size_t)(n0 + r1) * D + c1;

    const uint32_t d0 = (uint32_t)(r0 * 80 + c0 * 2);
    const uint32_t d1 = (uint32_t)(r1 * 80 + c1 * 2);

    auto issue = [&](int st, int ch) {
        const int off = ch * 32;
        const uint32_t b = sS + st * STG;
        cpa16(b + d0, Ag0 + off);
        cpa16(b + d1, Ag1 + off);
        cpa16(b + TILE_B + d0, Bg0 + off);
        cpa16(b + TILE_B + d1, Bg1 + off);
    };

    issue(0, 0); CP_COMMIT();
    issue(1, 1); CP_COMMIT();
    issue(2, 2); CP_COMMIT();
    issue(3, 3); CP_COMMIT();

    const uint32_t a_off = (uint32_t)((wm + (lane & 15)) * 80 + (lane >> 4) * 16);
    const uint32_t b_off = (uint32_t)(TILE_B +
                                      (wn + (lane & 15)) * 80 + (lane >> 4) * 16);

    float acc[4][4][4];
#pragma unroll
    for (int i = 0; i < 4; i++)
#pragma unroll
        for (int j = 0; j < 4; j++)
#pragma unroll
            for (int u = 0; u < 4; u++) acc[i][j][u] = 0.f;

    int rd = 0, wr = 4;
    for (int c = 0; c < NCH; c++) {
        if (c + 4 < NCH) issue(wr, c + 4);
        CP_COMMIT();
        CP_WAIT(4);
        __syncthreads();

        const uint32_t sbase = sS + (uint32_t)(rd * STG);
#pragma unroll
        for (int kk = 0; kk < 2; kk++) {
            uint32_t af[4][4], bf[2][4];
#pragma unroll
            for (int mt = 0; mt < 4; mt++)
                ldsm_x4(af[mt], sbase + a_off + (uint32_t)(mt * 16 * 80 + kk * 32));
#pragma unroll
            for (int nb = 0; nb < 2; nb++)
                ldsm_x4(bf[nb], sbase + b_off + (uint32_t)(nb * 16 * 80 + kk * 32));
#pragma unroll
            for (int mt = 0; mt < 4; mt++)
#pragma unroll
                for (int n8 = 0; n8 < 4; n8++) {
                    const int nb = n8 >> 1, hi = n8 & 1;
                    mma16816(acc[mt][n8], af[mt],
                             bf[nb][hi ? 1 : 0], bf[nb][hi ? 3 : 2]);
                }
        }
        __syncthreads();
        rd = (rd + 1) % 5;
        wr = (wr + 1) % 5;
    }

    const int er = lane >> 2;
    const int ec = (lane & 3) * 2;
#pragma unroll
    for (int mt = 0; mt < 4; mt++) {
#pragma unroll
        for (int n8 = 0; n8 < 4; n8++) {
            const int row = m0 + wm + mt * 16 + er;
            const int col = n0 + wn + n8 * 8 + ec;
            if (MODE == 0) {
                float2 bb = *(const float2*)&bias[col];
                *(float2*)&C[(size_t)row * D + col] =
                    make_float2(acc[mt][n8][0] + bb.x, acc[mt][n8][1] + bb.y);
                *(float2*)&C[(size_t)(row + 8) * D + col] =
                    make_float2(acc[mt][n8][2] + bb.x, acc[mt][n8][3] + bb.y);
            } else {
                const int h = col >> 6, d = col & 63;
                *(uint32_t*)&Cb[((size_t)row * HEADS + h) * 64 + d] =
                    packh(acc[mt][n8][0] * scale, acc[mt][n8][1] * scale);
                *(uint32_t*)&Cb[((size_t)(row + 8) * HEADS + h) * 64 + d] =
                    packh(acc[mt][n8][2] * scale, acc[mt][n8][3] * scale);
            }
        }
    }
}

// ---------------------------------------------------------------------------
// Flash attention, fixed-max softmax via ex2.approx.f16x2, 128-query tile,
// 8 warps, 4-stage 64-key cp.async K/V pipeline (three tiles in flight).
// smem: qs 18432 + ks 4x9216 + vs 4x9216 = 92160 B (2 CTAs/SM).
// ---------------------------------------------------------------------------
__global__ __launch_bounds__(256, 2)
void flash_mma(const __half* __restrict__ qc,
               const __half* __restrict__ kc,
               const __half* __restrict__ vc,
               __half* __restrict__ cc)
{
    extern __shared__ __half fsm[];
    __half* qs = fsm;                              // 128*72
    const uint32_t qs_b = smem_u32(fsm);
    const uint32_t ks_b = qs_b + 18432u;
    const uint32_t vs_b = ks_b + 36864u;           // 4 stages of 9216

    const int t = threadIdx.x, lane = t & 31, w = t >> 5;
    const int qt = (int)gridDim.x - 1 - (int)blockIdx.x;   // heavy blocks first
    const int b  = blockIdx.y >> 4, h = blockIdx.y & 15;
    const int q0 = qt * 128;
    const size_t tokbase = (size_t)b * SEQ;

    auto issueKV = [&](int kt) {
        const int s = kt & 3;
        const __half* kg = kc + ((tokbase + kt * 64) * HEADS + h) * 64;
        const __half* vg = vc + ((tokbase + kt * 64) * HEADS + h) * 64;
#pragma unroll
        for (int p = 0; p < 2; p++) {
            int idx = p * 256 + t;
            int row = idx >> 3, c8 = idx & 7;
            uint32_t doff = (uint32_t)(s * 9216 + row * 144 + c8 * 16);
            size_t soff = (size_t)row * (HEADS * 64) + c8 * 8;
            cpa16(ks_b + doff, kg + soff);
            cpa16(vs_b + doff, vg + soff);
        }
    };

    // load Q tile: 128 rows x 64 halves = 1024 8-half chunks
    const __half* qg = qc + ((tokbase + q0) * HEADS + h) * 64;
#pragma unroll
    for (int it = 0; it < 4; it++) {
        int idx = it * 256 + t;
        int row = idx >> 3, c8 = (idx & 7) * 8;
        *(uint4*)&qs[row * 72 + c8] =
            *(const uint4*)&qg[(size_t)row * (HEADS * 64) + c8];
    }
    const int n_kt = 2 * qt + 2;
    issueKV(0); CP_COMMIT();
    issueKV(1); CP_COMMIT();               // n_kt >= 2 always
    if (2 < n_kt) issueKV(2);
    CP_COMMIT();
    __syncthreads();

    uint32_t qf[4][4];
    const uint32_t qbase = qs_b +
        (uint32_t)((w * 16 + (lane & 15)) * 144 + (lane >> 4) * 16);
#pragma unroll
    for (int c = 0; c < 4; c++) ldsm_x4(qf[c], qbase + c * 32);

    const int er = lane >> 2, ec = (lane & 3) * 2;
    const int wq_min = q0 + w * 16;
    float l0 = 0.f, l1 = 0.f;
    float oa[8][4];
#pragma unroll
    for (int i = 0; i < 8; i++)
#pragma unroll
        for (int j = 0; j < 4; j++) oa[i][j] = 0.f;

    for (int kt = 0; kt < n_kt; kt++) {
        if (kt + 3 < n_kt) issueKV(kt + 3);
        CP_COMMIT();
        CP_WAIT(3);
        __syncthreads();

        const int k0 = kt * 64;
        const int s = kt & 3;

        if (k0 <= wq_min + 15) {
            // ---- S = Q K^T (log2 domain) ----
            float sa[8][4];
#pragma unroll
            for (int i = 0; i < 8; i++)
#pragma unroll
                for (int j = 0; j < 4; j++) sa[i][j] = 0.f;

            const uint32_t kb = ks_b + (uint32_t)(s * 9216) +
                (uint32_t)((lane & 15) * 144 + (lane >> 4) * 16);
#pragma unroll
            for (int nb = 0; nb < 4; nb++) {
                const uint32_t roff = (uint32_t)(nb * 16 * 144);
#pragma unroll
                for (int c = 0; c < 4; c++) {
                    uint32_t bf_[4];
                    ldsm_x4(bf_, kb + roff + c * 32);
                    mma16816(sa[nb * 2],     qf[c], bf_[0], bf_[2]);
                    mma16816(sa[nb * 2 + 1], qf[c], bf_[1], bf_[3]);
                }
            }

            // ---- causal mask (finite large-negative -> fp16 flush to 0) ----
            if (k0 + 63 > wq_min) {
                const int gq0 = wq_min + er;
#pragma unroll
                for (int n8 = 0; n8 < 8; n8++) {
                    const int gk = k0 + n8 * 8 + ec;
                    if (gk > gq0)         sa[n8][0] = MASK_NEG;
                    if (gk + 1 > gq0)     sa[n8][1] = MASK_NEG;
                    if (gk > gq0 + 8)     sa[n8][2] = MASK_NEG;
                    if (gk + 1 > gq0 + 8) sa[n8][3] = MASK_NEG;
                }
            }

            // ---- p = 2^s in fp16 pairs; packed P = PV A-fragments ----
            uint32_t p01[8], p23[8];
            __half2 lh0 = __floats2half2_rn(0.f, 0.f);
            __half2 lh1 = lh0;
#pragma unroll
            for (int n8 = 0; n8 < 8; n8++) {
                p01[n8] = ex2_h2(packh(sa[n8][0], sa[n8][1]));
                p23[n8] = ex2_h2(packh(sa[n8][2], sa[n8][3]));
                lh0 = __hadd2(lh0, *(__half2*)&p01[n8]);
                lh1 = __hadd2(lh1, *(__half2*)&p23[n8]);
            }
            float2 lf0 = __half22float2(lh0);
            float2 lf1 = __half22float2(lh1);
            l0 += lf0.x + lf0.y;
            l1 += lf1.x + lf1.y;

            // ---- O += P V ----
            const uint32_t vb0 = vs_b + (uint32_t)(s * 9216) +
                (uint32_t)((lane & 15) * 144 + (lane >> 4) * 16);
#pragma unroll
            for (int c = 0; c < 4; c++) {
                uint32_t ah[4];
                ah[0] = p01[2 * c];
                ah[1] = p23[2 * c];
                ah[2] = p01[2 * c + 1];
                ah[3] = p23[2 * c + 1];
                const uint32_t kroff = (uint32_t)(c * 16 * 144);
#pragma unroll
                for (int vb = 0; vb < 4; vb++) {
                    uint32_t bf_[4];
                    ldsm_x4t(bf_, vb0 + kroff + vb * 32);
                    mma16816(oa[vb * 2],     ah, bf_[0], bf_[1]);
                    mma16816(oa[vb * 2 + 1], ah, bf_[2], bf_[3]);
                }
            }
        }
        __syncthreads();
    }

    // ---- final row-sum reduction across the 4-lane quad ----
    l0 += __shfl_xor_sync(0xffffffffu, l0, 1);
    l0 += __shfl_xor_sync(0xffffffffu, l0, 2);
    l1 += __shfl_xor_sync(0xffffffffu, l1, 1);
    l1 += __shfl_xor_sync(0xffffffffu, l1, 2);

    // ---- epilogue: ctx = O / l -> cc [tok][1024] fp16 ----
    const float il0 = 1.f / l0, il1 = 1.f / l1;
    const int gq0 = wq_min + er;
    const size_t rbase0 = (tokbase + gq0) * (size_t)D;
    const size_t rbase1 = (tokbase + gq0 + 8) * (size_t)D;
#pragma unroll
    for (int n8 = 0; n8 < 8; n8++) {
        const int col = h * 64 + n8 * 8 + ec;
        *(uint32_t*)&cc[rbase0 + col] = packh(oa[n8][0] * il0, oa[n8][1] * il0);
        *(uint32_t*)&cc[rbase1 + col] = packh(oa[n8][2] * il1, oa[n8][3] * il1);
    }
}

// ---------------------------------------------------------------------------
extern "C" void kernel_launch(void* const* d_in, const int* in_sizes, int n_in,
                              void* d_out, int out_size)
{
    const float* x  = (const float*)d_in[0];
    const float* Wq = (const float*)d_in[1];
    const float* Wk = (const float*)d_in[2];
    const float* Wv = (const float*)d_in[3];
    const float* Wo = (const float*)d_in[4];
    const float* bo = (const float*)d_in[5];
    float* out = (float*)d_out;

    __half *xc, *cc, *wqt, *wkt, *wvt, *wot, *qc, *kc, *vc;
    cudaGetSymbolAddress((void**)&xc,  g_xc);
    cudaGetSymbolAddress((void**)&cc,  g_cc);
    cudaGetSymbolAddress((void**)&wqt, g_wqt);
    cudaGetSymbolAddress((void**)&wkt, g_wkt);
    cudaGetSymbolAddress((void**)&wvt, g_wvt);
    cudaGetSymbolAddress((void**)&wot, g_wot);
    cudaGetSymbolAddress((void**)&qc,  g_qc);
    cudaGetSymbolAddress((void**)&kc,  g_kc);
    cudaGetSymbolAddress((void**)&vc,  g_vc);

    const int GEMM_SMEM  = 5 * 2 * TILE_B;              // 102400 B (5 stages)
    const int FLASH_SMEM = 18432 + 2 * 36864;           // 92160 B
    cudaFuncSetAttribute(gemm_1t<0>,
        cudaFuncAttributeMaxDynamicSharedMemorySize, GEMM_SMEM);
    cudaFuncSetAttribute(gemm_1t<1>,
        cudaFuncAttributeMaxDynamicSharedMemorySize, GEMM_SMEM);
    cudaFuncSetAttribute(flash_mma,
        cudaFuncAttributeMaxDynamicSharedMemorySize, FLASH_SMEM);

    convert_all<<<dim3(32, 32, 5), 256>>>(x, Wq, Wk, Wv, Wo,
                                          xc, wqt, wkt, wvt, wot);

    gemm_1t<1><<<dim3(D / 128, TOK / 128, 3), 256, GEMM_SMEM>>>(
        xc, wqt, wkt, wvt, nullptr, nullptr, qc, kc, vc);

    flash_mma<<<dim3(SEQ / 128, 2 * HEADS), 256, FLASH_SMEM>>>(qc, kc, vc, cc);

    gemm_1t<0><<<dim3(D / 128, TOK / 128), 256, GEMM_SMEM>>>(
        cc, wot, nullptr, nullptr, bo, out, nullptr, nullptr, nullptr);
}

// round 15
// speedup vs baseline: 1.4399x; 1.0590x over previous
#include <cuda_runtime.h>
#include <cuda_fp16.h>
#include <math_constants.h>
#include <cstdint>

// ---------------------------------------------------------------------------
// MultiHeadAttention, GB300 (family PTX -> mma.sync HMMA):
//   Round 15: single-barrier pipelines — 5-stage rings with issue distance 3
//   ((d+1) % S != 0 -> no write/read stage collision under warp skew), for
//   both GEMMs and flash. Otherwise identical to round 14.
// ---------------------------------------------------------------------------

namespace {
constexpr int TOK   = 4096;
constexpr int D     = 1024;
constexpr int HEADS = 16;
constexpr int SEQ   = 2048;
constexpr int NCH   = D / 32;           // 32 K-chunks of 32
constexpr int TILE_B = 128 * 80;        // 128x32 fp16 tile, 80B rows (10240 B)
constexpr float MASK_NEG = -60.0f;      // 2^-60 -> 0 in fp16
}

// ------------------------------ scratch -----------------------------------
__device__ __half g_xc[TOK * D];               // x fp16
__device__ __half g_cc[TOK * D];               // ctx fp16
__device__ __half g_wqt[D * D];                // W^T fp16
__device__ __half g_wkt[D * D];
__device__ __half g_wvt[D * D];
__device__ __half g_wot[D * D];
__device__ __half g_qc[TOK * HEADS * 64];      // per-head, x(0.125*log2e)
__device__ __half g_kc[TOK * HEADS * 64];
__device__ __half g_vc[TOK * HEADS * 64];

// --------------------------- PTX helpers -----------------------------------
__device__ __forceinline__ uint32_t smem_u32(const void* p) {
    uint32_t a;
    asm("{ .reg .u64 t; cvta.to.shared.u64 t, %1; cvt.u32.u64 %0, t; }"
        : "=r"(a) : "l"(p));
    return a;
}
__device__ __forceinline__ void ldsm_x4(uint32_t* r, uint32_t addr) {
    asm volatile("ldmatrix.sync.aligned.m8n8.x4.shared.b16 {%0,%1,%2,%3}, [%4];"
                 : "=r"(r[0]), "=r"(r[1]), "=r"(r[2]), "=r"(r[3]) : "r"(addr));
}
__device__ __forceinline__ void ldsm_x4t(uint32_t* r, uint32_t addr) {
    asm volatile("ldmatrix.sync.aligned.m8n8.x4.trans.shared.b16 {%0,%1,%2,%3}, [%4];"
                 : "=r"(r[0]), "=r"(r[1]), "=r"(r[2]), "=r"(r[3]) : "r"(addr));
}
__device__ __forceinline__ void mma16816(float* d, const uint32_t* a,
                                         uint32_t b0, uint32_t b1) {
    asm volatile(
        "mma.sync.aligned.m16n8k16.row.col.f32.f16.f16.f32 "
        "{%0,%1,%2,%3}, {%4,%5,%6,%7}, {%8,%9}, {%0,%1,%2,%3};"
        : "+f"(d[0]), "+f"(d[1]), "+f"(d[2]), "+f"(d[3])
        : "r"(a[0]), "r"(a[1]), "r"(a[2]), "r"(a[3]), "r"(b0), "r"(b1));
}
__device__ __forceinline__ uint32_t packh(float a, float b) {
    __half2 h = __floats2half2_rn(a, b);
    return *(uint32_t*)&h;
}
__device__ __forceinline__ uint32_t ex2_h2(uint32_t s) {
    uint32_t r;
    asm("ex2.approx.f16x2 %0, %1;" : "=r"(r) : "r"(s));
    return r;
}
__device__ __forceinline__ void cpa16(uint32_t dst, const void* src) {
    asm volatile("cp.async.cg.shared.global [%0], [%1], 16;"
                 :: "r"(dst), "l"(src) : "memory");
}
#define CP_COMMIT() asm volatile("cp.async.commit_group;" ::: "memory")
#define CP_WAIT(N)  asm volatile("cp.async.wait_group %0;" :: "n"(N) : "memory")

// ---------------------------------------------------------------------------
// Merged converts: z=0..3 weight transpose, z=4 x convert.
// ---------------------------------------------------------------------------
__global__ void convert_all(const float* __restrict__ x,
                            const float* __restrict__ W0,
                            const float* __restrict__ W1,
                            const float* __restrict__ W2,
                            const float* __restrict__ W3,
                            __half* __restrict__ xc,
                            __half* __restrict__ T0,
                            __half* __restrict__ T1,
                            __half* __restrict__ T2,
                            __half* __restrict__ T3)
{
    const int z = blockIdx.z;
    if (z == 4) {
        int idx = (blockIdx.y * 32 + blockIdx.x) * 256 + threadIdx.x;
        const int stride = 32 * 32 * 256;
#pragma unroll
        for (int i = 0; i < TOK * D / (32 * 32 * 256); i++) {
            xc[idx] = __float2half_rn(x[idx]);
            idx += stride;
        }
        return;
    }
    __shared__ float tile[32][33];
    const float* W = z == 0 ? W0 : (z == 1 ? W1 : (z == 2 ? W2 : W3));
    __half* Wt = z == 0 ? T0 : (z == 1 ? T1 : (z == 2 ? T2 : T3));

    const int k0 = blockIdx.y * 32;
    const int n0 = blockIdx.x * 32;
    const int tx = threadIdx.x & 31;
    const int ty = threadIdx.x >> 5;
#pragma unroll
    for (int p = 0; p < 4; p++)
        tile[ty + p * 8][tx] = W[(size_t)(k0 + ty + p * 8) * D + n0 + tx];
    __syncthreads();
#pragma unroll
    for (int p = 0; p < 4; p++) {
        int n = n0 + ty + p * 8;
        Wt[(size_t)n * D + k0 + tx] = __float2half_rn(tile[tx][ty + p * 8]);
    }
}

// ---------------------------------------------------------------------------
// Single-term fp16 GEMM: 128x128 tile, BK=32, 8 warps, 5-stage ring with
// issue distance 3 and ONE barrier per chunk.
// MODE 1 (QKV): z picks W / out / scale; per-head fp16 out.
// MODE 0 (out): fp32 out + bias.
// ---------------------------------------------------------------------------
template <int MODE>
__global__ __launch_bounds__(256)
void gemm_1t(const __half* __restrict__ A,
             const __half* __restrict__ B0,
             const __half* __restrict__ B1,
             const __half* __restrict__ B2,
             const float* __restrict__ bias,
             float* __restrict__ C,
             __half* __restrict__ O0,
             __half* __restrict__ O1,
             __half* __restrict__ O2)
{
    extern __shared__ char dsm[];
    const uint32_t sS = smem_u32(dsm);
    constexpr uint32_t STG = 2 * TILE_B;     // A tile + B tile (20480 B)

    const int t = threadIdx.x, lane = t & 31, warp = t >> 5;
    const int wm = (warp & 1) * 64, wn = (warp >> 1) * 32;
    const int m0 = blockIdx.y * 128, n0 = blockIdx.x * 128;

    const __half* Bt;
    __half* Cb = nullptr;
    float scale = 1.f;
    int z = 0;
    if (MODE == 1) {
        z = blockIdx.z;
        Bt = z == 0 ? B0 : (z == 1 ? B1 : B2);
        Cb = z == 0 ? O0 : (z == 1 ? O1 : O2);
        scale = (z == 0) ? 0.125f * 1.44269504f : 1.f;   // fold log2(e) into Q
    } else {
        Bt = B0;
    }

    const int r0 = t >> 2,         c0 = (t & 3) * 8;
    const int r1 = (t + 256) >> 2, c1 = ((t + 256) & 3) * 8;

    const __half* Ag0 = A  + (size_t)(m0 + r0) * D + c0;
    const __half* Ag1 = A  + (size_t)(m0 + r1) * D + c1;
    const __half* Bg0 = Bt + (size_t)(n0 + r0) * D + c0;
    const __half* Bg1 = Bt + (size_t)(n0 + r1) * D + c1;

    const uint32_t d0 = (uint32_t)(r0 * 80 + c0 * 2);
    const uint32_t d1 = (uint32_t)(r1 * 80 + c1 * 2);

    auto issue = [&](int st, int ch) {
        const int off = ch * 32;
        const uint32_t b = sS + st * STG;
        cpa16(b + d0, Ag0 + off);
        cpa16(b + d1, Ag1 + off);
        cpa16(b + TILE_B + d0, Bg0 + off);
        cpa16(b + TILE_B + d1, Bg1 + off);
    };

    issue(0, 0); CP_COMMIT();
    issue(1, 1); CP_COMMIT();
    issue(2, 2); CP_COMMIT();

    const uint32_t a_off = (uint32_t)((wm + (lane & 15)) * 80 + (lane >> 4) * 16);
    const uint32_t b_off = (uint32_t)(TILE_B +
                                      (wn + (lane & 15)) * 80 + (lane >> 4) * 16);

    float acc[4][4][4];
#pragma unroll
    for (int i = 0; i < 4; i++)
#pragma unroll
        for (int j = 0; j < 4; j++)
#pragma unroll
            for (int u = 0; u < 4; u++) acc[i][j][u] = 0.f;

    int rd = 0, wr = 3;
    for (int c = 0; c < NCH; c++) {
        if (c + 3 < NCH) issue(wr, c + 3);
        CP_COMMIT();
        CP_WAIT(3);
        __syncthreads();                      // single barrier per chunk

        const uint32_t sbase = sS + (uint32_t)(rd * STG);
#pragma unroll
        for (int kk = 0; kk < 2; kk++) {
            uint32_t af[4][4], bf[2][4];
#pragma unroll
            for (int mt = 0; mt < 4; mt++)
                ldsm_x4(af[mt], sbase + a_off + (uint32_t)(mt * 16 * 80 + kk * 32));
#pragma unroll
            for (int nb = 0; nb < 2; nb++)
                ldsm_x4(bf[nb], sbase + b_off + (uint32_t)(nb * 16 * 80 + kk * 32));
#pragma unroll
            for (int mt = 0; mt < 4; mt++)
#pragma unroll
                for (int n8 = 0; n8 < 4; n8++) {
                    const int nb = n8 >> 1, hi = n8 & 1;
                    mma16816(acc[mt][n8], af[mt],
                             bf[nb][hi ? 1 : 0], bf[nb][hi ? 3 : 2]);
                }
        }
        rd = (rd + 1) % 5;
        wr = (wr + 1) % 5;
    }

    const int er = lane >> 2;
    const int ec = (lane & 3) * 2;
#pragma unroll
    for (int mt = 0; mt < 4; mt++) {
#pragma unroll
        for (int n8 = 0; n8 < 4; n8++) {
            const int row = m0 + wm + mt * 16 + er;
            const int col = n0 + wn + n8 * 8 + ec;
            if (MODE == 0) {
                float2 bb = *(const float2*)&bias[col];
                *(float2*)&C[(size_t)row * D + col] =
                    make_float2(acc[mt][n8][0] + bb.x, acc[mt][n8][1] + bb.y);
                *(float2*)&C[(size_t)(row + 8) * D + col] =
                    make_float2(acc[mt][n8][2] + bb.x, acc[mt][n8][3] + bb.y);
            } else {
                const int h = col >> 6, d = col & 63;
                *(uint32_t*)&Cb[((size_t)row * HEADS + h) * 64 + d] =
                    packh(acc[mt][n8][0] * scale, acc[mt][n8][1] * scale);
                *(uint32_t*)&Cb[((size_t)(row + 8) * HEADS + h) * 64 + d] =
                    packh(acc[mt][n8][2] * scale, acc[mt][n8][3] * scale);
            }
        }
    }
}

// ---------------------------------------------------------------------------
// Flash attention, fixed-max softmax via ex2.approx.f16x2, 128-query tile,
// 8 warps, 5-stage 64-key K/V ring with issue distance 3, ONE barrier/tile.
// smem: qs 18432 + ks 5x9216 + vs 5x9216 = 110592 B (2 CTAs/SM).
// ---------------------------------------------------------------------------
__global__ __launch_bounds__(256, 2)
void flash_mma(const __half* __restrict__ qc,
               const __half* __restrict__ kc,
               const __half* __restrict__ vc,
               __half* __restrict__ cc)
{
    extern __shared__ __half fsm[];
    __half* qs = fsm;                              // 128*72
    const uint32_t qs_b = smem_u32(fsm);
    const uint32_t ks_b = qs_b + 18432u;
    const uint32_t vs_b = ks_b + 46080u;           // 5 stages of 9216

    const int t = threadIdx.x, lane = t & 31, w = t >> 5;
    const int qt = (int)gridDim.x - 1 - (int)blockIdx.x;   // heavy blocks first
    const int b  = blockIdx.y >> 4, h = blockIdx.y & 15;
    const int q0 = qt * 128;
    const size_t tokbase = (size_t)b * SEQ;

    auto issueKV = [&](int kt) {
        const int s = kt % 5;
        const __half* kg = kc + ((tokbase + kt * 64) * HEADS + h) * 64;
        const __half* vg = vc + ((tokbase + kt * 64) * HEADS + h) * 64;
#pragma unroll
        for (int p = 0; p < 2; p++) {
            int idx = p * 256 + t;
            int row = idx >> 3, c8 = idx & 7;
            uint32_t doff = (uint32_t)(s * 9216 + row * 144 + c8 * 16);
            size_t soff = (size_t)row * (HEADS * 64) + c8 * 8;
            cpa16(ks_b + doff, kg + soff);
            cpa16(vs_b + doff, vg + soff);
        }
    };

    // load Q tile: 128 rows x 64 halves = 1024 8-half chunks
    const __half* qg = qc + ((tokbase + q0) * HEADS + h) * 64;
#pragma unroll
    for (int it = 0; it < 4; it++) {
        int idx = it * 256 + t;
        int row = idx >> 3, c8 = (idx & 7) * 8;
        *(uint4*)&qs[row * 72 + c8] =
            *(const uint4*)&qg[(size_t)row * (HEADS * 64) + c8];
    }
    const int n_kt = 2 * qt + 2;
    issueKV(0); CP_COMMIT();
    issueKV(1); CP_COMMIT();               // n_kt >= 2 always
    if (2 < n_kt) issueKV(2);
    CP_COMMIT();
    __syncthreads();

    uint32_t qf[4][4];
    const uint32_t qbase = qs_b +
        (uint32_t)((w * 16 + (lane & 15)) * 144 + (lane >> 4) * 16);
#pragma unroll
    for (int c = 0; c < 4; c++) ldsm_x4(qf[c], qbase + c * 32);

    const int er = lane >> 2, ec = (lane & 3) * 2;
    const int wq_min = q0 + w * 16;
    float l0 = 0.f, l1 = 0.f;
    float oa[8][4];
#pragma unroll
    for (int i = 0; i < 8; i++)
#pragma unroll
        for (int j = 0; j < 4; j++) oa[i][j] = 0.f;

    for (int kt = 0; kt < n_kt; kt++) {
        if (kt + 3 < n_kt) issueKV(kt + 3);
        CP_COMMIT();
        CP_WAIT(3);
        __syncthreads();                      // single barrier per key tile

        const int k0 = kt * 64;
        const int s = kt % 5;

        if (k0 <= wq_min + 15) {
            // ---- S = Q K^T (log2 domain) ----
            float sa[8][4];
#pragma unroll
            for (int i = 0; i < 8; i++)
#pragma unroll
                for (int j = 0; j < 4; j++) sa[i][j] = 0.f;

            const uint32_t kb = ks_b + (uint32_t)(s * 9216) +
                (uint32_t)((lane & 15) * 144 + (lane >> 4) * 16);
#pragma unroll
            for (int nb = 0; nb < 4; nb++) {
                const uint32_t roff = (uint32_t)(nb * 16 * 144);
#pragma unroll
                for (int c = 0; c < 4; c++) {
                    uint32_t bf_[4];
                    ldsm_x4(bf_, kb + roff + c * 32);
                    mma16816(sa[nb * 2],     qf[c], bf_[0], bf_[2]);
                    mma16816(sa[nb * 2 + 1], qf[c], bf_[1], bf_[3]);
                }
            }

            // ---- causal mask (finite large-negative -> fp16 flush to 0) ----
            if (k0 + 63 > wq_min) {
                const int gq0 = wq_min + er;
#pragma unroll
                for (int n8 = 0; n8 < 8; n8++) {
                    const int gk = k0 + n8 * 8 + ec;
                    if (gk > gq0)         sa[n8][0] = MASK_NEG;
                    if (gk + 1 > gq0)     sa[n8][1] = MASK_NEG;
                    if (gk > gq0 + 8)     sa[n8][2] = MASK_NEG;
                    if (gk + 1 > gq0 + 8) sa[n8][3] = MASK_NEG;
                }
            }

            // ---- p = 2^s in fp16 pairs; packed P = PV A-fragments ----
            uint32_t p01[8], p23[8];
            __half2 lh0 = __floats2half2_rn(0.f, 0.f);
            __half2 lh1 = lh0;
#pragma unroll
            for (int n8 = 0; n8 < 8; n8++) {
                p01[n8] = ex2_h2(packh(sa[n8][0], sa[n8][1]));
                p23[n8] = ex2_h2(packh(sa[n8][2], sa[n8][3]));
                lh0 = __hadd2(lh0, *(__half2*)&p01[n8]);
                lh1 = __hadd2(lh1, *(__half2*)&p23[n8]);
            }
            float2 lf0 = __half22float2(lh0);
            float2 lf1 = __half22float2(lh1);
            l0 += lf0.x + lf0.y;
            l1 += lf1.x + lf1.y;

            // ---- O += P V ----
            const uint32_t vb0 = vs_b + (uint32_t)(s * 9216) +
                (uint32_t)((lane & 15) * 144 + (lane >> 4) * 16);
#pragma unroll
            for (int c = 0; c < 4; c++) {
                uint32_t ah[4];
                ah[0] = p01[2 * c];
                ah[1] = p23[2 * c];
                ah[2] = p01[2 * c + 1];
                ah[3] = p23[2 * c + 1];
                const uint32_t kroff = (uint32_t)(c * 16 * 144);
#pragma unroll
                for (int vb = 0; vb < 4; vb++) {
                    uint32_t bf_[4];
                    ldsm_x4t(bf_, vb0 + kroff + vb * 32);
                    mma16816(oa[vb * 2],     ah, bf_[0], bf_[1]);
                    mma16816(oa[vb * 2 + 1], ah, bf_[2], bf_[3]);
                }
            }
        }
    }

    // ---- final row-sum reduction across the 4-lane quad ----
    l0 += __shfl_xor_sync(0xffffffffu, l0, 1);
    l0 += __shfl_xor_sync(0xffffffffu, l0, 2);
    l1 += __shfl_xor_sync(0xffffffffu, l1, 1);
    l1 += __shfl_xor_sync(0xffffffffu, l1, 2);

    // ---- epilogue: ctx = O / l -> cc [tok][1024] fp16 ----
    const float il0 = 1.f / l0, il1 = 1.f / l1;
    const int gq0 = wq_min + er;
    const size_t rbase0 = (tokbase + gq0) * (size_t)D;
    const size_t rbase1 = (tokbase + gq0 + 8) * (size_t)D;
#pragma unroll
    for (int n8 = 0; n8 < 8; n8++) {
        const int col = h * 64 + n8 * 8 + ec;
        *(uint32_t*)&cc[rbase0 + col] = packh(oa[n8][0] * il0, oa[n8][1] * il0);
        *(uint32_t*)&cc[rbase1 + col] = packh(oa[n8][2] * il1, oa[n8][3] * il1);
    }
}

// ---------------------------------------------------------------------------
extern "C" void kernel_launch(void* const* d_in, const int* in_sizes, int n_in,
                              void* d_out, int out_size)
{
    const float* x  = (const float*)d_in[0];
    const float* Wq = (const float*)d_in[1];
    const float* Wk = (const float*)d_in[2];
    const float* Wv = (const float*)d_in[3];
    const float* Wo = (const float*)d_in[4];
    const float* bo = (const float*)d_in[5];
    float* out = (float*)d_out;

    __half *xc, *cc, *wqt, *wkt, *wvt, *wot, *qc, *kc, *vc;
    cudaGetSymbolAddress((void**)&xc,  g_xc);
    cudaGetSymbolAddress((void**)&cc,  g_cc);
    cudaGetSymbolAddress((void**)&wqt, g_wqt);
    cudaGetSymbolAddress((void**)&wkt, g_wkt);
    cudaGetSymbolAddress((void**)&wvt, g_wvt);
    cudaGetSymbolAddress((void**)&wot, g_wot);
    cudaGetSymbolAddress((void**)&qc,  g_qc);
    cudaGetSymbolAddress((void**)&kc,  g_kc);
    cudaGetSymbolAddress((void**)&vc,  g_vc);

    const int GEMM_SMEM  = 5 * 2 * TILE_B;              // 102400 B (5 stages)
    const int FLASH_SMEM = 18432 + 2 * 46080;           // 110592 B
    cudaFuncSetAttribute(gemm_1t<0>,
        cudaFuncAttributeMaxDynamicSharedMemorySize, GEMM_SMEM);
    cudaFuncSetAttribute(gemm_1t<1>,
        cudaFuncAttributeMaxDynamicSharedMemorySize, GEMM_SMEM);
    cudaFuncSetAttribute(flash_mma,
        cudaFuncAttributeMaxDynamicSharedMemorySize, FLASH_SMEM);

    convert_all<<<dim3(32, 32, 5), 256>>>(x, Wq, Wk, Wv, Wo,
                                          xc, wqt, wkt, wvt, wot);

    gemm_1t<1><<<dim3(D / 128, TOK / 128, 3), 256, GEMM_SMEM>>>(
        xc, wqt, wkt, wvt, nullptr, nullptr, qc, kc, vc);

    flash_mma<<<dim3(SEQ / 128, 2 * HEADS), 256, FLASH_SMEM>>>(qc, kc, vc, cc);

    gemm_1t<0><<<dim3(D / 128, TOK / 128), 256, GEMM_SMEM>>>(
        cc, wot, nullptr, nullptr, bo, out, nullptr, nullptr, nullptr);
}

// round 16
// speedup vs baseline: 1.5365x; 1.0671x over previous
#include <cuda_runtime.h>
#include <cuda_fp16.h>
#include <math_constants.h>
#include <cstdint>

// ---------------------------------------------------------------------------
// MultiHeadAttention, GB300 (family PTX -> mma.sync HMMA):
//   Round 16: GEMMs restructured to 64x128 CTA tiles (32x32 warp tile,
//   32 acc regs) -> natural fit for 3 CTAs/SM (24 warps). 4-stage ring,
//   depth 3, issue-after-barrier single-barrier pipeline.
//   Flash/converts unchanged from round 15.
// ---------------------------------------------------------------------------

namespace {
constexpr int TOK   = 4096;
constexpr int D     = 1024;
constexpr int HEADS = 16;
constexpr int SEQ   = 2048;
constexpr int NCH   = D / 32;           // 32 K-chunks of 32
constexpr int GA_B  = 64 * 80;          // GEMM A tile: 64 rows x 80B (5120 B)
constexpr int GB_B  = 128 * 80;         // GEMM B tile: 128 rows x 80B (10240 B)
constexpr int GSTG  = GA_B + GB_B;      // 15360 B per stage
constexpr float MASK_NEG = -60.0f;      // 2^-60 -> 0 in fp16
}

// ------------------------------ scratch -----------------------------------
__device__ __half g_xc[TOK * D];               // x fp16
__device__ __half g_cc[TOK * D];               // ctx fp16
__device__ __half g_wqt[D * D];                // W^T fp16
__device__ __half g_wkt[D * D];
__device__ __half g_wvt[D * D];
__device__ __half g_wot[D * D];
__device__ __half g_qc[TOK * HEADS * 64];      // per-head, x(0.125*log2e)
__device__ __half g_kc[TOK * HEADS * 64];
__device__ __half g_vc[TOK * HEADS * 64];

// --------------------------- PTX helpers -----------------------------------
__device__ __forceinline__ uint32_t smem_u32(const void* p) {
    uint32_t a;
    asm("{ .reg .u64 t; cvta.to.shared.u64 t, %1; cvt.u32.u64 %0, t; }"
        : "=r"(a) : "l"(p));
    return a;
}
__device__ __forceinline__ void ldsm_x4(uint32_t* r, uint32_t addr) {
    asm volatile("ldmatrix.sync.aligned.m8n8.x4.shared.b16 {%0,%1,%2,%3}, [%4];"
                 : "=r"(r[0]), "=r"(r[1]), "=r"(r[2]), "=r"(r[3]) : "r"(addr));
}
__device__ __forceinline__ void ldsm_x4t(uint32_t* r, uint32_t addr) {
    asm volatile("ldmatrix.sync.aligned.m8n8.x4.trans.shared.b16 {%0,%1,%2,%3}, [%4];"
                 : "=r"(r[0]), "=r"(r[1]), "=r"(r[2]), "=r"(r[3]) : "r"(addr));
}
__device__ __forceinline__ void mma16816(float* d, const uint32_t* a,
                                         uint32_t b0, uint32_t b1) {
    asm volatile(
        "mma.sync.aligned.m16n8k16.row.col.f32.f16.f16.f32 "
        "{%0,%1,%2,%3}, {%4,%5,%6,%7}, {%8,%9}, {%0,%1,%2,%3};"
        : "+f"(d[0]), "+f"(d[1]), "+f"(d[2]), "+f"(d[3])
        : "r"(a[0]), "r"(a[1]), "r"(a[2]), "r"(a[3]), "r"(b0), "r"(b1));
}
__device__ __forceinline__ uint32_t packh(float a, float b) {
    __half2 h = __floats2half2_rn(a, b);
    return *(uint32_t*)&h;
}
__device__ __forceinline__ uint32_t ex2_h2(uint32_t s) {
    uint32_t r;
    asm("ex2.approx.f16x2 %0, %1;" : "=r"(r) : "r"(s));
    return r;
}
__device__ __forceinline__ void cpa16(uint32_t dst, const void* src) {
    asm volatile("cp.async.cg.shared.global [%0], [%1], 16;"
                 :: "r"(dst), "l"(src) : "memory");
}
#define CP_COMMIT() asm volatile("cp.async.commit_group;" ::: "memory")
#define CP_WAIT(N)  asm volatile("cp.async.wait_group %0;" :: "n"(N) : "memory")

// ---------------------------------------------------------------------------
// Merged converts: z=0..3 weight transpose, z=4 x convert.
// ---------------------------------------------------------------------------
__global__ void convert_all(const float* __restrict__ x,
                            const float* __restrict__ W0,
                            const float* __restrict__ W1,
                            const float* __restrict__ W2,
                            const float* __restrict__ W3,
                            __half* __restrict__ xc,
                            __half* __restrict__ T0,
                            __half* __restrict__ T1,
                            __half* __restrict__ T2,
                            __half* __restrict__ T3)
{
    const int z = blockIdx.z;
    if (z == 4) {
        int idx = (blockIdx.y * 32 + blockIdx.x) * 256 + threadIdx.x;
        const int stride = 32 * 32 * 256;
#pragma unroll
        for (int i = 0; i < TOK * D / (32 * 32 * 256); i++) {
            xc[idx] = __float2half_rn(x[idx]);
            idx += stride;
        }
        return;
    }
    __shared__ float tile[32][33];
    const float* W = z == 0 ? W0 : (z == 1 ? W1 : (z == 2 ? W2 : W3));
    __half* Wt = z == 0 ? T0 : (z == 1 ? T1 : (z == 2 ? T2 : T3));

    const int k0 = blockIdx.y * 32;
    const int n0 = blockIdx.x * 32;
    const int tx = threadIdx.x & 31;
    const int ty = threadIdx.x >> 5;
#pragma unroll
    for (int p = 0; p < 4; p++)
        tile[ty + p * 8][tx] = W[(size_t)(k0 + ty + p * 8) * D + n0 + tx];
    __syncthreads();
#pragma unroll
    for (int p = 0; p < 4; p++) {
        int n = n0 + ty + p * 8;
        Wt[(size_t)n * D + k0 + tx] = __float2half_rn(tile[tx][ty + p * 8]);
    }
}

// ---------------------------------------------------------------------------
// Single-term fp16 GEMM: 64x128 CTA tile, BK=32, 8 warps (2Mx4N -> 32x32
// warp tile, 32 acc regs), 4-stage ring depth 3, issue-after-barrier,
// 3 CTAs/SM.
// MODE 1 (QKV): z picks W / out / scale; per-head fp16 out.
// MODE 0 (out): fp32 out + bias.
// ---------------------------------------------------------------------------
template <int MODE>
__global__ __launch_bounds__(256, 3)
void gemm_1t(const __half* __restrict__ A,
             const __half* __restrict__ B0,
             const __half* __restrict__ B1,
             const __half* __restrict__ B2,
             const float* __restrict__ bias,
             float* __restrict__ C,
             __half* __restrict__ O0,
             __half* __restrict__ O1,
             __half* __restrict__ O2)
{
    extern __shared__ char dsm[];
    const uint32_t sS = smem_u32(dsm);

    const int t = threadIdx.x, lane = t & 31, warp = t >> 5;
    const int wm = (warp & 1) * 32, wn = (warp >> 1) * 32;
    const int m0 = blockIdx.y * 64, n0 = blockIdx.x * 128;

    const __half* Bt;
    __half* Cb = nullptr;
    float scale = 1.f;
    int z = 0;
    if (MODE == 1) {
        z = blockIdx.z;
        Bt = z == 0 ? B0 : (z == 1 ? B1 : B2);
        Cb = z == 0 ? O0 : (z == 1 ? O1 : O2);
        scale = (z == 0) ? 0.125f * 1.44269504f : 1.f;   // fold log2(e) into Q
    } else {
        Bt = B0;
    }

    // loaders: A 256 16B-chunks (1/thread), B 512 (2/thread)
    const int lr = t >> 2;             // 0..63
    const int lk = (t & 3);            // 16B chunk within 64B row
    const uint32_t sda = (uint32_t)(lr * 80 + lk * 16);

    const __half* Ag  = A  + (size_t)(m0 + lr) * D + lk * 8;
    const __half* Bg0 = Bt + (size_t)(n0 + lr) * D + lk * 8;
    const __half* Bg1 = Bt + (size_t)(n0 + 64 + lr) * D + lk * 8;

    auto issue = [&](int st, int ch) {
        const int off = ch * 32;
        const uint32_t b = sS + st * GSTG;
        cpa16(b + sda, Ag + off);
        cpa16(b + GA_B + sda, Bg0 + off);
        cpa16(b + GA_B + sda + (uint32_t)(64 * 80), Bg1 + off);
    };

    issue(0, 0); CP_COMMIT();
    issue(1, 1); CP_COMMIT();
    issue(2, 2); CP_COMMIT();

    const uint32_t a_off = (uint32_t)((wm + (lane & 15)) * 80 + (lane >> 4) * 16);
    const uint32_t b_off = (uint32_t)(GA_B +
                                      (wn + (lane & 15)) * 80 + (lane >> 4) * 16);

    float acc[2][4][4];
#pragma unroll
    for (int i = 0; i < 2; i++)
#pragma unroll
        for (int j = 0; j < 4; j++)
#pragma unroll
            for (int u = 0; u < 4; u++) acc[i][j][u] = 0.f;

    for (int c = 0; c < NCH; c++) {
        CP_WAIT(2);
        __syncthreads();                         // single barrier per chunk
        if (c + 3 < NCH) issue((c + 3) & 3, c + 3);
        CP_COMMIT();                             // keep group count uniform

        const uint32_t sbase = sS + (uint32_t)((c & 3) * GSTG);
#pragma unroll
        for (int kk = 0; kk < 2; kk++) {
            uint32_t af[2][4], bf[2][4];
#pragma unroll
            for (int mt = 0; mt < 2; mt++)
                ldsm_x4(af[mt], sbase + a_off + (uint32_t)(mt * 16 * 80 + kk * 32));
#pragma unroll
            for (int nb = 0; nb < 2; nb++)
                ldsm_x4(bf[nb], sbase + b_off + (uint32_t)(nb * 16 * 80 + kk * 32));
#pragma unroll
            for (int mt = 0; mt < 2; mt++)
#pragma unroll
                for (int n8 = 0; n8 < 4; n8++) {
                    const int nb = n8 >> 1, hi = n8 & 1;
                    mma16816(acc[mt][n8], af[mt],
                             bf[nb][hi ? 1 : 0], bf[nb][hi ? 3 : 2]);
                }
        }
    }

    const int er = lane >> 2;
    const int ec = (lane & 3) * 2;
#pragma unroll
    for (int mt = 0; mt < 2; mt++) {
#pragma unroll
        for (int n8 = 0; n8 < 4; n8++) {
            const int row = m0 + wm + mt * 16 + er;
            const int col = n0 + wn + n8 * 8 + ec;
            if (MODE == 0) {
                float2 bb = *(const float2*)&bias[col];
                *(float2*)&C[(size_t)row * D + col] =
                    make_float2(acc[mt][n8][0] + bb.x, acc[mt][n8][1] + bb.y);
                *(float2*)&C[(size_t)(row + 8) * D + col] =
                    make_float2(acc[mt][n8][2] + bb.x, acc[mt][n8][3] + bb.y);
            } else {
                const int h = col >> 6, d = col & 63;
                *(uint32_t*)&Cb[((size_t)row * HEADS + h) * 64 + d] =
                    packh(acc[mt][n8][0] * scale, acc[mt][n8][1] * scale);
                *(uint32_t*)&Cb[((size_t)(row + 8) * HEADS + h) * 64 + d] =
                    packh(acc[mt][n8][2] * scale, acc[mt][n8][3] * scale);
            }
        }
    }
}

// ---------------------------------------------------------------------------
// Flash attention (round-15 version, unchanged): fixed-max softmax via
// ex2.approx.f16x2, 128-query tile, 8 warps, 5-stage 64-key ring d=3,
// single barrier per tile. smem 110592 B (2 CTAs/SM).
// ---------------------------------------------------------------------------
__global__ __launch_bounds__(256, 2)
void flash_mma(const __half* __restrict__ qc,
               const __half* __restrict__ kc,
               const __half* __restrict__ vc,
               __half* __restrict__ cc)
{
    extern __shared__ __half fsm[];
    __half* qs = fsm;                              // 128*72
    const uint32_t qs_b = smem_u32(fsm);
    const uint32_t ks_b = qs_b + 18432u;
    const uint32_t vs_b = ks_b + 46080u;           // 5 stages of 9216

    const int t = threadIdx.x, lane = t & 31, w = t >> 5;
    const int qt = (int)gridDim.x - 1 - (int)blockIdx.x;   // heavy blocks first
    const int b  = blockIdx.y >> 4, h = blockIdx.y & 15;
    const int q0 = qt * 128;
    const size_t tokbase = (size_t)b * SEQ;

    auto issueKV = [&](int kt) {
        const int s = kt % 5;
        const __half* kg = kc + ((tokbase + kt * 64) * HEADS + h) * 64;
        const __half* vg = vc + ((tokbase + kt * 64) * HEADS + h) * 64;
#pragma unroll
        for (int p = 0; p < 2; p++) {
            int idx = p * 256 + t;
            int row = idx >> 3, c8 = idx & 7;
            uint32_t doff = (uint32_t)(s * 9216 + row * 144 + c8 * 16);
            size_t soff = (size_t)row * (HEADS * 64) + c8 * 8;
            cpa16(ks_b + doff, kg + soff);
            cpa16(vs_b + doff, vg + soff);
        }
    };

    const __half* qg = qc + ((tokbase + q0) * HEADS + h) * 64;
#pragma unroll
    for (int it = 0; it < 4; it++) {
        int idx = it * 256 + t;
        int row = idx >> 3, c8 = (idx & 7) * 8;
        *(uint4*)&qs[row * 72 + c8] =
            *(const uint4*)&qg[(size_t)row * (HEADS * 64) + c8];
    }
    const int n_kt = 2 * qt + 2;
    issueKV(0); CP_COMMIT();
    issueKV(1); CP_COMMIT();
    if (2 < n_kt) issueKV(2);
    CP_COMMIT();
    __syncthreads();

    uint32_t qf[4][4];
    const uint32_t qbase = qs_b +
        (uint32_t)((w * 16 + (lane & 15)) * 144 + (lane >> 4) * 16);
#pragma unroll
    for (int c = 0; c < 4; c++) ldsm_x4(qf[c], qbase + c * 32);

    const int er = lane >> 2, ec = (lane & 3) * 2;
    const int wq_min = q0 + w * 16;
    float l0 = 0.f, l1 = 0.f;
    float oa[8][4];
#pragma unroll
    for (int i = 0; i < 8; i++)
#pragma unroll
        for (int j = 0; j < 4; j++) oa[i][j] = 0.f;

    for (int kt = 0; kt < n_kt; kt++) {
        if (kt + 3 < n_kt) issueKV(kt + 3);
        CP_COMMIT();
        CP_WAIT(3);
        __syncthreads();

        const int k0 = kt * 64;
        const int s = kt % 5;

        if (k0 <= wq_min + 15) {
            float sa[8][4];
#pragma unroll
            for (int i = 0; i < 8; i++)
#pragma unroll
                for (int j = 0; j < 4; j++) sa[i][j] = 0.f;

            const uint32_t kb = ks_b + (uint32_t)(s * 9216) +
                (uint32_t)((lane & 15) * 144 + (lane >> 4) * 16);
#pragma unroll
            for (int nb = 0; nb < 4; nb++) {
                const uint32_t roff = (uint32_t)(nb * 16 * 144);
#pragma unroll
                for (int c = 0; c < 4; c++) {
                    uint32_t bf_[4];
                    ldsm_x4(bf_, kb + roff + c * 32);
                    mma16816(sa[nb * 2],     qf[c], bf_[0], bf_[2]);
                    mma16816(sa[nb * 2 + 1], qf[c], bf_[1], bf_[3]);
                }
            }

            if (k0 + 63 > wq_min) {
                const int gq0 = wq_min + er;
#pragma unroll
                for (int n8 = 0; n8 < 8; n8++) {
                    const int gk = k0 + n8 * 8 + ec;
                    if (gk > gq0)         sa[n8][0] = MASK_NEG;
                    if (gk + 1 > gq0)     sa[n8][1] = MASK_NEG;
                    if (gk > gq0 + 8)     sa[n8][2] = MASK_NEG;
                    if (gk + 1 > gq0 + 8) sa[n8][3] = MASK_NEG;
                }
            }

            uint32_t p01[8], p23[8];
            __half2 lh0 = __floats2half2_rn(0.f, 0.f);
            __half2 lh1 = lh0;
#pragma unroll
            for (int n8 = 0; n8 < 8; n8++) {
                p01[n8] = ex2_h2(packh(sa[n8][0], sa[n8][1]));
                p23[n8] = ex2_h2(packh(sa[n8][2], sa[n8][3]));
                lh0 = __hadd2(lh0, *(__half2*)&p01[n8]);
                lh1 = __hadd2(lh1, *(__half2*)&p23[n8]);
            }
            float2 lf0 = __half22float2(lh0);
            float2 lf1 = __half22float2(lh1);
            l0 += lf0.x + lf0.y;
            l1 += lf1.x + lf1.y;

            const uint32_t vb0 = vs_b + (uint32_t)(s * 9216) +
                (uint32_t)((lane & 15) * 144 + (lane >> 4) * 16);
#pragma unroll
            for (int c = 0; c < 4; c++) {
                uint32_t ah[4];
                ah[0] = p01[2 * c];
                ah[1] = p23[2 * c];
                ah[2] = p01[2 * c + 1];
                ah[3] = p23[2 * c + 1];
                const uint32_t kroff = (uint32_t)(c * 16 * 144);
#pragma unroll
                for (int vb = 0; vb < 4; vb++) {
                    uint32_t bf_[4];
                    ldsm_x4t(bf_, vb0 + kroff + vb * 32);
                    mma16816(oa[vb * 2],     ah, bf_[0], bf_[1]);
                    mma16816(oa[vb * 2 + 1], ah, bf_[2], bf_[3]);
                }
            }
        }
    }

    l0 += __shfl_xor_sync(0xffffffffu, l0, 1);
    l0 += __shfl_xor_sync(0xffffffffu, l0, 2);
    l1 += __shfl_xor_sync(0xffffffffu, l1, 1);
    l1 += __shfl_xor_sync(0xffffffffu, l1, 2);

    const float il0 = 1.f / l0, il1 = 1.f / l1;
    const int gq0 = wq_min + er;
    const size_t rbase0 = (tokbase + gq0) * (size_t)D;
    const size_t rbase1 = (tokbase + gq0 + 8) * (size_t)D;
#pragma unroll
    for (int n8 = 0; n8 < 8; n8++) {
        const int col = h * 64 + n8 * 8 + ec;
        *(uint32_t*)&cc[rbase0 + col] = packh(oa[n8][0] * il0, oa[n8][1] * il0);
        *(uint32_t*)&cc[rbase1 + col] = packh(oa[n8][2] * il1, oa[n8][3] * il1);
    }
}

// ---------------------------------------------------------------------------
extern "C" void kernel_launch(void* const* d_in, const int* in_sizes, int n_in,
                              void* d_out, int out_size)
{
    const float* x  = (const float*)d_in[0];
    const float* Wq = (const float*)d_in[1];
    const float* Wk = (const float*)d_in[2];
    const float* Wv = (const float*)d_in[3];
    const float* Wo = (const float*)d_in[4];
    const float* bo = (const float*)d_in[5];
    float* out = (float*)d_out;

    __half *xc, *cc, *wqt, *wkt, *wvt, *wot, *qc, *kc, *vc;
    cudaGetSymbolAddress((void**)&xc,  g_xc);
    cudaGetSymbolAddress((void**)&cc,  g_cc);
    cudaGetSymbolAddress((void**)&wqt, g_wqt);
    cudaGetSymbolAddress((void**)&wkt, g_wkt);
    cudaGetSymbolAddress((void**)&wvt, g_wvt);
    cudaGetSymbolAddress((void**)&wot, g_wot);
    cudaGetSymbolAddress((void**)&qc,  g_qc);
    cudaGetSymbolAddress((void**)&kc,  g_kc);
    cudaGetSymbolAddress((void**)&vc,  g_vc);

    const int GEMM_SMEM  = 4 * GSTG;                    // 61440 B (4 stages)
    const int FLASH_SMEM = 18432 + 2 * 46080;           // 110592 B
    cudaFuncSetAttribute(gemm_1t<0>,
        cudaFuncAttributeMaxDynamicSharedMemorySize, GEMM_SMEM);
    cudaFuncSetAttribute(gemm_1t<1>,
        cudaFuncAttributeMaxDynamicSharedMemorySize, GEMM_SMEM);
    cudaFuncSetAttribute(flash_mma,
        cudaFuncAttributeMaxDynamicSharedMemorySize, FLASH_SMEM);

    convert_all<<<dim3(32, 32, 5), 256>>>(x, Wq, Wk, Wv, Wo,
                                          xc, wqt, wkt, wvt, wot);

    gemm_1t<1><<<dim3(D / 128, TOK / 64, 3), 256, GEMM_SMEM>>>(
        xc, wqt, wkt, wvt, nullptr, nullptr, qc, kc, vc);

    flash_mma<<<dim3(SEQ / 128, 2 * HEADS), 256, FLASH_SMEM>>>(qc, kc, vc, cc);

    gemm_1t<0><<<dim3(D / 128, TOK / 64), 256, GEMM_SMEM>>>(
        cc, wot, nullptr, nullptr, bo, out, nullptr, nullptr, nullptr);
}

// round 17
// speedup vs baseline: 1.5485x; 1.0079x over previous
#include <cuda_runtime.h>
#include <cuda_fp16.h>
#include <math_constants.h>
#include <cstdint>

// ---------------------------------------------------------------------------
// MultiHeadAttention, GB300 (family PTX -> mma.sync HMMA):
//   Round 17: round-16 structure + smem-staged coalesced epilogues in all
//   three kernels (scattered 4-8B mma-layout stores -> 16B contiguous).
// ---------------------------------------------------------------------------

namespace {
constexpr int TOK   = 4096;
constexpr int D     = 1024;
constexpr int HEADS = 16;
constexpr int SEQ   = 2048;
constexpr int NCH   = D / 32;           // 32 K-chunks of 32
constexpr int GA_B  = 64 * 80;          // GEMM A tile: 64 rows x 80B (5120 B)
constexpr int GB_B  = 128 * 80;         // GEMM B tile: 128 rows x 80B (10240 B)
constexpr int GSTG  = GA_B + GB_B;      // 15360 B per stage
constexpr float MASK_NEG = -60.0f;      // 2^-60 -> 0 in fp16
}

// ------------------------------ scratch -----------------------------------
__device__ __half g_xc[TOK * D];               // x fp16
__device__ __half g_cc[TOK * D];               // ctx fp16
__device__ __half g_wqt[D * D];                // W^T fp16
__device__ __half g_wkt[D * D];
__device__ __half g_wvt[D * D];
__device__ __half g_wot[D * D];
__device__ __half g_qc[TOK * HEADS * 64];      // per-head, x(0.125*log2e)
__device__ __half g_kc[TOK * HEADS * 64];
__device__ __half g_vc[TOK * HEADS * 64];

// --------------------------- PTX helpers -----------------------------------
__device__ __forceinline__ uint32_t smem_u32(const void* p) {
    uint32_t a;
    asm("{ .reg .u64 t; cvta.to.shared.u64 t, %1; cvt.u32.u64 %0, t; }"
        : "=r"(a) : "l"(p));
    return a;
}
__device__ __forceinline__ void ldsm_x4(uint32_t* r, uint32_t addr) {
    asm volatile("ldmatrix.sync.aligned.m8n8.x4.shared.b16 {%0,%1,%2,%3}, [%4];"
                 : "=r"(r[0]), "=r"(r[1]), "=r"(r[2]), "=r"(r[3]) : "r"(addr));
}
__device__ __forceinline__ void ldsm_x4t(uint32_t* r, uint32_t addr) {
    asm volatile("ldmatrix.sync.aligned.m8n8.x4.trans.shared.b16 {%0,%1,%2,%3}, [%4];"
                 : "=r"(r[0]), "=r"(r[1]), "=r"(r[2]), "=r"(r[3]) : "r"(addr));
}
__device__ __forceinline__ void mma16816(float* d, const uint32_t* a,
                                         uint32_t b0, uint32_t b1) {
    asm volatile(
        "mma.sync.aligned.m16n8k16.row.col.f32.f16.f16.f32 "
        "{%0,%1,%2,%3}, {%4,%5,%6,%7}, {%8,%9}, {%0,%1,%2,%3};"
        : "+f"(d[0]), "+f"(d[1]), "+f"(d[2]), "+f"(d[3])
        : "r"(a[0]), "r"(a[1]), "r"(a[2]), "r"(a[3]), "r"(b0), "r"(b1));
}
__device__ __forceinline__ uint32_t packh(float a, float b) {
    __half2 h = __floats2half2_rn(a, b);
    return *(uint32_t*)&h;
}
__device__ __forceinline__ uint32_t ex2_h2(uint32_t s) {
    uint32_t r;
    asm("ex2.approx.f16x2 %0, %1;" : "=r"(r) : "r"(s));
    return r;
}
__device__ __forceinline__ void cpa16(uint32_t dst, const void* src) {
    asm volatile("cp.async.cg.shared.global [%0], [%1], 16;"
                 :: "r"(dst), "l"(src) : "memory");
}
#define CP_COMMIT() asm volatile("cp.async.commit_group;" ::: "memory")
#define CP_WAIT(N)  asm volatile("cp.async.wait_group %0;" :: "n"(N) : "memory")

// ---------------------------------------------------------------------------
// Merged converts: z=0..3 weight transpose, z=4 x convert.
// ---------------------------------------------------------------------------
__global__ void convert_all(const float* __restrict__ x,
                            const float* __restrict__ W0,
                            const float* __restrict__ W1,
                            const float* __restrict__ W2,
                            const float* __restrict__ W3,
                            __half* __restrict__ xc,
                            __half* __restrict__ T0,
                            __half* __restrict__ T1,
                            __half* __restrict__ T2,
                            __half* __restrict__ T3)
{
    const int z = blockIdx.z;
    if (z == 4) {
        int idx = (blockIdx.y * 32 + blockIdx.x) * 256 + threadIdx.x;
        const int stride = 32 * 32 * 256;
#pragma unroll
        for (int i = 0; i < TOK * D / (32 * 32 * 256); i++) {
            xc[idx] = __float2half_rn(x[idx]);
            idx += stride;
        }
        return;
    }
    __shared__ float tile[32][33];
    const float* W = z == 0 ? W0 : (z == 1 ? W1 : (z == 2 ? W2 : W3));
    __half* Wt = z == 0 ? T0 : (z == 1 ? T1 : (z == 2 ? T2 : T3));

    const int k0 = blockIdx.y * 32;
    const int n0 = blockIdx.x * 32;
    const int tx = threadIdx.x & 31;
    const int ty = threadIdx.x >> 5;
#pragma unroll
    for (int p = 0; p < 4; p++)
        tile[ty + p * 8][tx] = W[(size_t)(k0 + ty + p * 8) * D + n0 + tx];
    __syncthreads();
#pragma unroll
    for (int p = 0; p < 4; p++) {
        int n = n0 + ty + p * 8;
        Wt[(size_t)n * D + k0 + tx] = __float2half_rn(tile[tx][ty + p * 8]);
    }
}

// ---------------------------------------------------------------------------
// Single-term fp16 GEMM: 64x128 CTA tile, BK=32, 8 warps (32x32 warp tile),
// 4-stage ring depth 3, single barrier per chunk, 3 CTAs/SM.
// Smem-staged coalesced epilogues (stage region = dead ring stages 0-2;
// final chunk reads stage 3 only).
// MODE 1 (QKV): z picks W / out / scale; per-head fp16 out.
// MODE 0 (out): fp32 out + bias.
// ---------------------------------------------------------------------------
template <int MODE>
__global__ __launch_bounds__(256, 3)
void gemm_1t(const __half* __restrict__ A,
             const __half* __restrict__ B0,
             const __half* __restrict__ B1,
             const __half* __restrict__ B2,
             const float* __restrict__ bias,
             float* __restrict__ C,
             __half* __restrict__ O0,
             __half* __restrict__ O1,
             __half* __restrict__ O2)
{
    extern __shared__ char dsm[];
    const uint32_t sS = smem_u32(dsm);

    const int t = threadIdx.x, lane = t & 31, warp = t >> 5;
    const int wm = (warp & 1) * 32, wn = (warp >> 1) * 32;
    const int m0 = blockIdx.y * 64, n0 = blockIdx.x * 128;

    const __half* Bt;
    __half* Cb = nullptr;
    float scale = 1.f;
    int z = 0;
    if (MODE == 1) {
        z = blockIdx.z;
        Bt = z == 0 ? B0 : (z == 1 ? B1 : B2);
        Cb = z == 0 ? O0 : (z == 1 ? O1 : O2);
        scale = (z == 0) ? 0.125f * 1.44269504f : 1.f;   // fold log2(e) into Q
    } else {
        Bt = B0;
    }

    const int lr = t >> 2;             // 0..63
    const int lk = (t & 3);            // 16B chunk within 64B row
    const uint32_t sda = (uint32_t)(lr * 80 + lk * 16);

    const __half* Ag  = A  + (size_t)(m0 + lr) * D + lk * 8;
    const __half* Bg0 = Bt + (size_t)(n0 + lr) * D + lk * 8;
    const __half* Bg1 = Bt + (size_t)(n0 + 64 + lr) * D + lk * 8;

    auto issue = [&](int st, int ch) {
        const int off = ch * 32;
        const uint32_t b = sS + st * GSTG;
        cpa16(b + sda, Ag + off);
        cpa16(b + GA_B + sda, Bg0 + off);
        cpa16(b + GA_B + sda + (uint32_t)(64 * 80), Bg1 + off);
    };

    issue(0, 0); CP_COMMIT();
    issue(1, 1); CP_COMMIT();
    issue(2, 2); CP_COMMIT();

    const uint32_t a_off = (uint32_t)((wm + (lane & 15)) * 80 + (lane >> 4) * 16);
    const uint32_t b_off = (uint32_t)(GA_B +
                                      (wn + (lane & 15)) * 80 + (lane >> 4) * 16);

    float acc[2][4][4];
#pragma unroll
    for (int i = 0; i < 2; i++)
#pragma unroll
        for (int j = 0; j < 4; j++)
#pragma unroll
            for (int u = 0; u < 4; u++) acc[i][j][u] = 0.f;

    for (int c = 0; c < NCH; c++) {
        CP_WAIT(2);
        __syncthreads();                         // single barrier per chunk
        if (c + 3 < NCH) issue((c + 3) & 3, c + 3);
        CP_COMMIT();

        const uint32_t sbase = sS + (uint32_t)((c & 3) * GSTG);
#pragma unroll
        for (int kk = 0; kk < 2; kk++) {
            uint32_t af[2][4], bf[2][4];
#pragma unroll
            for (int mt = 0; mt < 2; mt++)
                ldsm_x4(af[mt], sbase + a_off + (uint32_t)(mt * 16 * 80 + kk * 32));
#pragma unroll
            for (int nb = 0; nb < 2; nb++)
                ldsm_x4(bf[nb], sbase + b_off + (uint32_t)(nb * 16 * 80 + kk * 32));
#pragma unroll
            for (int mt = 0; mt < 2; mt++)
#pragma unroll
                for (int n8 = 0; n8 < 4; n8++) {
                    const int nb = n8 >> 1, hi = n8 & 1;
                    mma16816(acc[mt][n8], af[mt],
                             bf[nb][hi ? 1 : 0], bf[nb][hi ? 3 : 2]);
                }
        }
    }

    // ---- smem-staged epilogue (stage region = ring stages 0-2, dead now) ----
    const int er = lane >> 2;
    const int ec = (lane & 3) * 2;

    if (MODE == 1) {
        // stage fp16: 64 rows x 128 halves, row stride 136 halves (272 B)
#pragma unroll
        for (int mt = 0; mt < 2; mt++)
#pragma unroll
            for (int n8 = 0; n8 < 4; n8++) {
                const int rl = wm + mt * 16 + er;
                const int cl = wn + n8 * 8 + ec;
                *(uint32_t*)(dsm + rl * 272 + cl * 2) =
                    packh(acc[mt][n8][0] * scale, acc[mt][n8][1] * scale);
                *(uint32_t*)(dsm + (rl + 8) * 272 + cl * 2) =
                    packh(acc[mt][n8][2] * scale, acc[mt][n8][3] * scale);
            }
        __syncthreads();
        const int h0 = n0 >> 6;
#pragma unroll
        for (int it = 0; it < 4; it++) {
            const int idx = it * 256 + t;
            const int row = idx >> 4, c16 = idx & 15;
            uint4 v = *(uint4*)(dsm + row * 272 + c16 * 16);
            *(uint4*)&Cb[((size_t)(m0 + row) * HEADS + h0 + (c16 >> 3)) * 64 +
                         (c16 & 7) * 8] = v;
        }
    } else {
        // stage fp32: 64 rows x 128 floats, row stride 132 floats (528 B)
#pragma unroll
        for (int mt = 0; mt < 2; mt++)
#pragma unroll
            for (int n8 = 0; n8 < 4; n8++) {
                const int rl = wm + mt * 16 + er;
                const int cl = wn + n8 * 8 + ec;
                *(float2*)(dsm + rl * 528 + cl * 4) =
                    make_float2(acc[mt][n8][0], acc[mt][n8][1]);
                *(float2*)(dsm + (rl + 8) * 528 + cl * 4) =
                    make_float2(acc[mt][n8][2], acc[mt][n8][3]);
            }
        __syncthreads();
#pragma unroll
        for (int it = 0; it < 8; it++) {
            const int idx = it * 256 + t;
            const int row = idx >> 5, c16 = idx & 31;
            float4 v = *(float4*)(dsm + row * 528 + c16 * 16);
            float4 bb = *(const float4*)&bias[n0 + c16 * 4];
            v.x += bb.x; v.y += bb.y; v.z += bb.z; v.w += bb.w;
            *(float4*)&C[(size_t)(m0 + row) * D + n0 + c16 * 4] = v;
        }
    }
}

// ---------------------------------------------------------------------------
// Flash attention (round-15/16 core): fixed-max softmax via ex2.approx.f16x2,
// 128-query tile, 8 warps, 5-stage 64-key ring d=3, single barrier per tile.
// NEW: epilogue staged through the dead Q-tile smem region, stored coalesced.
// ---------------------------------------------------------------------------
__global__ __launch_bounds__(256, 2)
void flash_mma(const __half* __restrict__ qc,
               const __half* __restrict__ kc,
               const __half* __restrict__ vc,
               __half* __restrict__ cc)
{
    extern __shared__ __half fsm[];
    __half* qs = fsm;                              // 128*72 (reused by epilogue)
    const uint32_t qs_b = smem_u32(fsm);
    const uint32_t ks_b = qs_b + 18432u;
    const uint32_t vs_b = ks_b + 46080u;           // 5 stages of 9216

    const int t = threadIdx.x, lane = t & 31, w = t >> 5;
    const int qt = (int)gridDim.x - 1 - (int)blockIdx.x;   // heavy blocks first
    const int b  = blockIdx.y >> 4, h = blockIdx.y & 15;
    const int q0 = qt * 128;
    const size_t tokbase = (size_t)b * SEQ;

    auto issueKV = [&](int kt) {
        const int s = kt % 5;
        const __half* kg = kc + ((tokbase + kt * 64) * HEADS + h) * 64;
        const __half* vg = vc + ((tokbase + kt * 64) * HEADS + h) * 64;
#pragma unroll
        for (int p = 0; p < 2; p++) {
            int idx = p * 256 + t;
            int row = idx >> 3, c8 = idx & 7;
            uint32_t doff = (uint32_t)(s * 9216 + row * 144 + c8 * 16);
            size_t soff = (size_t)row * (HEADS * 64) + c8 * 8;
            cpa16(ks_b + doff, kg + soff);
            cpa16(vs_b + doff, vg + soff);
        }
    };

    const __half* qg = qc + ((tokbase + q0) * HEADS + h) * 64;
#pragma unroll
    for (int it = 0; it < 4; it++) {
        int idx = it * 256 + t;
        int row = idx >> 3, c8 = (idx & 7) * 8;
        *(uint4*)&qs[row * 72 + c8] =
            *(const uint4*)&qg[(size_t)row * (HEADS * 64) + c8];
    }
    const int n_kt = 2 * qt + 2;
    issueKV(0); CP_COMMIT();
    issueKV(1); CP_COMMIT();
    if (2 < n_kt) issueKV(2);
    CP_COMMIT();
    __syncthreads();

    uint32_t qf[4][4];
    const uint32_t qbase = qs_b +
        (uint32_t)((w * 16 + (lane & 15)) * 144 + (lane >> 4) * 16);
#pragma unroll
    for (int c = 0; c < 4; c++) ldsm_x4(qf[c], qbase + c * 32);

    const int er = lane >> 2, ec = (lane & 3) * 2;
    const int wq_min = q0 + w * 16;
    float l0 = 0.f, l1 = 0.f;
    float oa[8][4];
#pragma unroll
    for (int i = 0; i < 8; i++)
#pragma unroll
        for (int j = 0; j < 4; j++) oa[i][j] = 0.f;

    for (int kt = 0; kt < n_kt; kt++) {
        if (kt + 3 < n_kt) issueKV(kt + 3);
        CP_COMMIT();
        CP_WAIT(3);
        __syncthreads();

        const int k0 = kt * 64;
        const int s = kt % 5;

        if (k0 <= wq_min + 15) {
            float sa[8][4];
#pragma unroll
            for (int i = 0; i < 8; i++)
#pragma unroll
                for (int j = 0; j < 4; j++) sa[i][j] = 0.f;

            const uint32_t kb = ks_b + (uint32_t)(s * 9216) +
                (uint32_t)((lane & 15) * 144 + (lane >> 4) * 16);
#pragma unroll
            for (int nb = 0; nb < 4; nb++) {
                const uint32_t roff = (uint32_t)(nb * 16 * 144);
#pragma unroll
                for (int c = 0; c < 4; c++) {
                    uint32_t bf_[4];
                    ldsm_x4(bf_, kb + roff + c * 32);
                    mma16816(sa[nb * 2],     qf[c], bf_[0], bf_[2]);
                    mma16816(sa[nb * 2 + 1], qf[c], bf_[1], bf_[3]);
                }
            }

            if (k0 + 63 > wq_min) {
                const int gq0 = wq_min + er;
#pragma unroll
                for (int n8 = 0; n8 < 8; n8++) {
                    const int gk = k0 + n8 * 8 + ec;
                    if (gk > gq0)         sa[n8][0] = MASK_NEG;
                    if (gk + 1 > gq0)     sa[n8][1] = MASK_NEG;
                    if (gk > gq0 + 8)     sa[n8][2] = MASK_NEG;
                    if (gk + 1 > gq0 + 8) sa[n8][3] = MASK_NEG;
                }
            }

            uint32_t p01[8], p23[8];
            __half2 lh0 = __floats2half2_rn(0.f, 0.f);
            __half2 lh1 = lh0;
#pragma unroll
            for (int n8 = 0; n8 < 8; n8++) {
                p01[n8] = ex2_h2(packh(sa[n8][0], sa[n8][1]));
                p23[n8] = ex2_h2(packh(sa[n8][2], sa[n8][3]));
                lh0 = __hadd2(lh0, *(__half2*)&p01[n8]);
                lh1 = __hadd2(lh1, *(__half2*)&p23[n8]);
            }
            float2 lf0 = __half22float2(lh0);
            float2 lf1 = __half22float2(lh1);
            l0 += lf0.x + lf0.y;
            l1 += lf1.x + lf1.y;

            const uint32_t vb0 = vs_b + (uint32_t)(s * 9216) +
                (uint32_t)((lane & 15) * 144 + (lane >> 4) * 16);
#pragma unroll
            for (int c = 0; c < 4; c++) {
                uint32_t ah[4];
                ah[0] = p01[2 * c];
                ah[1] = p23[2 * c];
                ah[2] = p01[2 * c + 1];
                ah[3] = p23[2 * c + 1];
                const uint32_t kroff = (uint32_t)(c * 16 * 144);
#pragma unroll
                for (int vb = 0; vb < 4; vb++) {
                    uint32_t bf_[4];
                    ldsm_x4t(bf_, vb0 + kroff + vb * 32);
                    mma16816(oa[vb * 2],     ah, bf_[0], bf_[1]);
                    mma16816(oa[vb * 2 + 1], ah, bf_[2], bf_[3]);
                }
            }
        }
    }

    l0 += __shfl_xor_sync(0xffffffffu, l0, 1);
    l0 += __shfl_xor_sync(0xffffffffu, l0, 2);
    l1 += __shfl_xor_sync(0xffffffffu, l1, 1);
    l1 += __shfl_xor_sync(0xffffffffu, l1, 2);

    // ---- epilogue: stage ctx/l into qs (warp-private rows), then coalesced ----
    const float il0 = 1.f / l0, il1 = 1.f / l1;
    const int rl = w * 16 + er;
#pragma unroll
    for (int n8 = 0; n8 < 8; n8++) {
        const int cl = n8 * 8 + ec;
        *(uint32_t*)&qs[rl * 72 + cl] =
            packh(oa[n8][0] * il0, oa[n8][1] * il0);
        *(uint32_t*)&qs[(rl + 8) * 72 + cl] =
            packh(oa[n8][2] * il1, oa[n8][3] * il1);
    }
    __syncthreads();
#pragma unroll
    for (int it = 0; it < 4; it++) {
        const int idx = it * 256 + t;
        const int row = idx >> 3, c8 = idx & 7;
        uint4 v = *(uint4*)&qs[row * 72 + c8 * 8];
        *(uint4*)&cc[(tokbase + q0 + row) * (size_t)D + h * 64 + c8 * 8] = v;
    }
}

// ---------------------------------------------------------------------------
extern "C" void kernel_launch(void* const* d_in, const int* in_sizes, int n_in,
                              void* d_out, int out_size)
{
    const float* x  = (const float*)d_in[0];
    const float* Wq = (const float*)d_in[1];
    const float* Wk = (const float*)d_in[2];
    const float* Wv = (const float*)d_in[3];
    const float* Wo = (const float*)d_in[4];
    const float* bo = (const float*)d_in[5];
    float* out = (float*)d_out;

    __half *xc, *cc, *wqt, *wkt, *wvt, *wot, *qc, *kc, *vc;
    cudaGetSymbolAddress((void**)&xc,  g_xc);
    cudaGetSymbolAddress((void**)&cc,  g_cc);
    cudaGetSymbolAddress((void**)&wqt, g_wqt);
    cudaGetSymbolAddress((void**)&wkt, g_wkt);
    cudaGetSymbolAddress((void**)&wvt, g_wvt);
    cudaGetSymbolAddress((void**)&wot, g_wot);
    cudaGetSymbolAddress((void**)&qc,  g_qc);
    cudaGetSymbolAddress((void**)&kc,  g_kc);
    cudaGetSymbolAddress((void**)&vc,  g_vc);

    const int GEMM_SMEM  = 4 * GSTG;                    // 61440 B
    const int FLASH_SMEM = 18432 + 2 * 46080;           // 110592 B
    cudaFuncSetAttribute(gemm_1t<0>,
        cudaFuncAttributeMaxDynamicSharedMemorySize, GEMM_SMEM);
    cudaFuncSetAttribute(gemm_1t<1>,
        cudaFuncAttributeMaxDynamicSharedMemorySize, GEMM_SMEM);
    cudaFuncSetAttribute(flash_mma,
        cudaFuncAttributeMaxDynamicSharedMemorySize, FLASH_SMEM);

    convert_all<<<dim3(32, 32, 5), 256>>>(x, Wq, Wk, Wv, Wo,
                                          xc, wqt, wkt, wvt, wot);

    gemm_1t<1><<<dim3(D / 128, TOK / 64, 3), 256, GEMM_SMEM>>>(
        xc, wqt, wkt, wvt, nullptr, nullptr, qc, kc, vc);

    flash_mma<<<dim3(SEQ / 128, 2 * HEADS), 256, FLASH_SMEM>>>(qc, kc, vc, cc);

    gemm_1t<0><<<dim3(D / 128, TOK / 64), 256, GEMM_SMEM>>>(
        cc, wot, nullptr, nullptr, bo, out, nullptr, nullptr, nullptr);
}